// round 4
// baseline (speedup 1.0000x reference)
#include <cuda_runtime.h>
#include <cstdint>
#include <cstddef>

// ---------------- problem constants ----------------
#define BATCH   4096
#define NTAB    26
#define DEMB    128
#define NTPER   81920      /* B*L indices per table */
#define EROWS   100000
#define FIN     3456       /* (T+1)*D */
#define LOWR    512

// ---------------- scratch (device globals; no runtime alloc) ----------------
__device__ float g_bot0[BATCH * 512];
__device__ float g_bot1[BATCH * 256];
__device__ float g_comb[BATCH * FIN];   // combined features (immutable after build)
__device__ float g_xl  [BATCH * FIN];   // DCN running state
__device__ float g_xv  [BATCH * LOWR];
__device__ float g_z0  [BATCH * 1024];
__device__ float g_z1  [BATCH * 1024];
__device__ float g_z2  [BATCH * 512];
__device__ int   g_is64;

// ---------------- dtype detection (int64 vs int32 indices/offsets) ----------
// If the buffer holds int64 values < 2^31, every odd 32-bit word is zero.
__global__ void detect_kernel(const unsigned* __restrict__ words, int n_elems) {
    __shared__ unsigned red;
    if (threadIdx.x == 0) red = 0u;
    __syncthreads();
    unsigned acc = 0u;
    for (int i = 1 + 2 * (int)threadIdx.x; i < n_elems; i += 2 * (int)blockDim.x)
        acc |= words[i];
    if (acc) atomicOr(&red, 1u);
    __syncthreads();
    if (threadIdx.x == 0) g_is64 = (red == 0u) ? 1 : 0;
}

// ---------------- embedding-bag pooling: one warp per (table, bag) ----------
__global__ void pool_kernel(const void* __restrict__ idxp,
                            const void* __restrict__ offp,
                            const float* __restrict__ tables,
                            float* __restrict__ comb) {
    int wg   = (blockIdx.x * blockDim.x + threadIdx.x) >> 5;
    int lane = threadIdx.x & 31;
    if (wg >= NTAB * BATCH) return;
    int t = wg / BATCH;
    int b = wg - t * BATCH;

    const int is64 = g_is64;
    long long lo, hi;
    if (is64) {
        const long long* off = (const long long*)offp + (size_t)t * BATCH;
        lo = (b == 0) ? 0 : off[b];
        hi = (b == BATCH - 1) ? (long long)NTPER : off[b + 1];
    } else {
        const int* off = (const int*)offp + (size_t)t * BATCH;
        lo = (b == 0) ? 0 : (long long)off[b];
        hi = (b == BATCH - 1) ? (long long)NTPER : (long long)off[b + 1];
    }

    const float* tab = tables + (size_t)t * EROWS * DEMB;
    float4 acc = make_float4(0.f, 0.f, 0.f, 0.f);
    if (is64) {
        const long long* idx = (const long long*)idxp + (size_t)t * NTPER;
        for (long long i = lo; i < hi; ++i) {
            long long r = idx[i];
            float4 v = *(const float4*)(tab + (size_t)r * DEMB + lane * 4);
            acc.x += v.x; acc.y += v.y; acc.z += v.z; acc.w += v.w;
        }
    } else {
        const int* idx = (const int*)idxp + (size_t)t * NTPER;
        for (long long i = lo; i < hi; ++i) {
            int r = idx[i];
            float4 v = *(const float4*)(tab + (size_t)r * DEMB + lane * 4);
            acc.x += v.x; acc.y += v.y; acc.z += v.z; acc.w += v.w;
        }
    }
    float* dst = comb + (size_t)b * FIN + (size_t)(t + 1) * DEMB + lane * 4;
    *(float4*)dst = acc;
}

// ---------------- generic NT SGEMM: C[M,N] = A[M,K] * B[N,K]^T -------------
// 128x128 tile, BK=8, 256 threads, 8x8 microtile. M,N tile-exact by launch.
// EPI: 0 = store acc, 1 = relu(acc + bias), 2 = DCN: comb*(acc+bias)+xlin
template<int EPI>
__global__ void __launch_bounds__(256, 2)
sgemm_nt(const float* __restrict__ A, int lda,
         const float* __restrict__ Bm, int ldb,
         const float* __restrict__ bias,
         float* __restrict__ C, int ldc,
         int K,
         const float* __restrict__ comb,
         const float* __restrict__ xlin) {
    __shared__ __align__(16) float As[8][128];
    __shared__ __align__(16) float Bs[8][128];

    const int tid = threadIdx.x;
    const int m0 = blockIdx.y * 128;
    const int n0 = blockIdx.x * 128;
    const int lr = tid >> 1;          // 0..127
    const int lc = (tid & 1) * 4;     // 0 or 4
    const float* Ag = A  + (size_t)(m0 + lr) * lda + lc;
    const float* Bg = Bm + (size_t)(n0 + lr) * ldb + lc;
    const int ty = tid >> 4;          // 0..15
    const int tx = tid & 15;          // 0..15

    float acc[8][8];
#pragma unroll
    for (int i = 0; i < 8; i++)
#pragma unroll
        for (int j = 0; j < 8; j++) acc[i][j] = 0.f;

    for (int k0 = 0; k0 < K; k0 += 8) {
#pragma unroll
        for (int j = 0; j < 4; j++) {
            int kk = k0 + lc + j;
            As[lc + j][lr] = (kk < K) ? Ag[k0 + j] : 0.f;
            Bs[lc + j][lr] = (kk < K) ? Bg[k0 + j] : 0.f;
        }
        __syncthreads();
#pragma unroll
        for (int k = 0; k < 8; k++) {
            float4 a0 = *(const float4*)&As[k][ty * 4];
            float4 a1 = *(const float4*)&As[k][64 + ty * 4];
            float4 b0 = *(const float4*)&Bs[k][tx * 4];
            float4 b1 = *(const float4*)&Bs[k][64 + tx * 4];
            float af[8] = {a0.x, a0.y, a0.z, a0.w, a1.x, a1.y, a1.z, a1.w};
            float bf[8] = {b0.x, b0.y, b0.z, b0.w, b1.x, b1.y, b1.z, b1.w};
#pragma unroll
            for (int i = 0; i < 8; i++)
#pragma unroll
                for (int j = 0; j < 8; j++)
                    acc[i][j] += af[i] * bf[j];
        }
        __syncthreads();
    }

#pragma unroll
    for (int i = 0; i < 8; i++) {
        int mg = m0 + ((i < 4) ? (ty * 4 + i) : (64 + ty * 4 + (i - 4)));
        size_t rowoff = (size_t)mg * ldc;
#pragma unroll
        for (int j = 0; j < 8; j++) {
            int ng = n0 + ((j < 4) ? (tx * 4 + j) : (64 + tx * 4 + (j - 4)));
            float v = acc[i][j];
            if (EPI == 1) {
                v += bias[ng];
                v = (v > 0.f) ? v : 0.f;
            } else if (EPI == 2) {
                v = comb[rowoff + ng] * (v + bias[ng]) + xlin[rowoff + ng];
            }
            C[rowoff + ng] = v;
        }
    }
}

// ---------------- final layer: out[b] = z2[b,:] . W3 + b3 ------------------
__global__ void final_kernel(const float* __restrict__ z,
                             const float* __restrict__ w,
                             const float* __restrict__ b3,
                             float* __restrict__ out) {
    int row = blockIdx.x;
    float s = 0.f;
    for (int j = threadIdx.x; j < 512; j += 128)
        s += z[(size_t)row * 512 + j] * w[j];
#pragma unroll
    for (int o = 16; o > 0; o >>= 1)
        s += __shfl_down_sync(0xffffffffu, s, o);
    __shared__ float sm[4];
    if ((threadIdx.x & 31) == 0) sm[threadIdx.x >> 5] = s;
    __syncthreads();
    if (threadIdx.x == 0)
        out[row] = sm[0] + sm[1] + sm[2] + sm[3] + b3[0];
}

// ---------------- launch ----------------------------------------------------
extern "C" void kernel_launch(void* const* d_in, const int* in_sizes, int n_in,
                              void* d_out, int out_size) {
    const float* dense   = (const float*)d_in[0];
    const void*  indices = d_in[1];
    const void*  offsets = d_in[2];
    const float* emb     = (const float*)d_in[3];
    const float* bW0 = (const float*)d_in[4];  const float* bb0 = (const float*)d_in[5];
    const float* bW1 = (const float*)d_in[6];  const float* bb1 = (const float*)d_in[7];
    const float* bW2 = (const float*)d_in[8];  const float* bb2 = (const float*)d_in[9];
    const float* dcnW = (const float*)d_in[10];
    const float* dcnV = (const float*)d_in[11];
    const float* dcnb = (const float*)d_in[12];
    const float* tW0 = (const float*)d_in[13]; const float* tb0 = (const float*)d_in[14];
    const float* tW1 = (const float*)d_in[15]; const float* tb1 = (const float*)d_in[16];
    const float* tW2 = (const float*)d_in[17]; const float* tb2 = (const float*)d_in[18];
    const float* tW3 = (const float*)d_in[19]; const float* tb3 = (const float*)d_in[20];

    float *bot0, *bot1, *comb, *xl, *xv, *z0, *z1, *z2;
    cudaGetSymbolAddress((void**)&bot0, g_bot0);
    cudaGetSymbolAddress((void**)&bot1, g_bot1);
    cudaGetSymbolAddress((void**)&comb, g_comb);
    cudaGetSymbolAddress((void**)&xl,   g_xl);
    cudaGetSymbolAddress((void**)&xv,   g_xv);
    cudaGetSymbolAddress((void**)&z0,   g_z0);
    cudaGetSymbolAddress((void**)&z1,   g_z1);
    cudaGetSymbolAddress((void**)&z2,   g_z2);

    // --- bottom MLP: 13 -> 512 -> 256 -> 128 (relu each), last into comb slot 0
    sgemm_nt<1><<<dim3(4, 32), 256>>>(dense, 13,  bW0, 13,  bb0, bot0, 512, 13,  nullptr, nullptr);
    sgemm_nt<1><<<dim3(2, 32), 256>>>(bot0, 512,  bW1, 512, bb1, bot1, 256, 512, nullptr, nullptr);
    sgemm_nt<1><<<dim3(1, 32), 256>>>(bot1, 256,  bW2, 256, bb2, comb, FIN, 256, nullptr, nullptr);

    // --- embedding-bag pooling into comb slots 1..26
    detect_kernel<<<1, 256>>>((const unsigned*)offsets, in_sizes[2]);
    pool_kernel<<<(NTAB * BATCH) / 8, 256>>>(indices, offsets, emb, comb);

    // --- low-rank DCN: 3 layers, G2 epilogue fuses comb*(xw+b)+x_l
    for (int l = 0; l < 3; l++) {
        const float* x = (l == 0) ? comb : xl;
        sgemm_nt<0><<<dim3(4, 32), 256>>>(x, FIN,
                                          dcnV + (size_t)l * LOWR * FIN, FIN,
                                          nullptr, xv, LOWR, FIN, nullptr, nullptr);
        sgemm_nt<2><<<dim3(27, 32), 256>>>(xv, LOWR,
                                           dcnW + (size_t)l * FIN * LOWR, LOWR,
                                           dcnb + (size_t)l * FIN,
                                           xl, FIN, LOWR, comb, x);
    }

    // --- top MLP: 3456 -> 1024 -> 1024 -> 512 (relu), -> 1
    sgemm_nt<1><<<dim3(8, 32), 256>>>(xl, FIN,  tW0, FIN,  tb0, z0, 1024, FIN,  nullptr, nullptr);
    sgemm_nt<1><<<dim3(8, 32), 256>>>(z0, 1024, tW1, 1024, tb1, z1, 1024, 1024, nullptr, nullptr);
    sgemm_nt<1><<<dim3(4, 32), 256>>>(z1, 1024, tW2, 1024, tb2, z2, 512,  1024, nullptr, nullptr);
    final_kernel<<<BATCH, 128>>>(z2, tW3, tb3, (float*)d_out);
}

// round 6
// speedup vs baseline: 2.9660x; 2.9660x over previous
#include <cuda_runtime.h>
#include <cuda_bf16.h>
#include <cstdint>
#include <cstddef>

typedef __nv_bfloat16 bf16;

// ---------------- problem constants ----------------
#define BATCH   4096
#define NTAB    26
#define DEMB    128
#define NTPER   81920
#define EROWS   100000
#define FIN     3456
#define LOWR    512
#define STAGES  4

// ---------------- scratch (device globals; no runtime alloc) ----------------
__device__ float g_bot0[BATCH * 512];
__device__ float g_bot1[BATCH * 256];
__device__ float g_comb[BATCH * FIN];        // combined features (fp32, immutable)
__device__ float g_xl  [BATCH * FIN];        // DCN running state (fp32)
__device__ float g_z2  [BATCH * 512];
__device__ int   g_is64;
__device__ bf16  g_act3 [BATCH * 3 * FIN];   // split activations, ld = 3*3456
__device__ bf16  g_act3b[BATCH * 3 * 1024];  // split z0
__device__ bf16  g_xv3  [BATCH * 3 * LOWR];  // split xv
__device__ bf16  g_wb3  [1024 * 3 * FIN];    // shared split-weight scratch (max tW0)

// ==================== PTX helpers ====================
__device__ __forceinline__ uint32_t smem_u32(const void* p) {
    uint32_t a;
    asm("{ .reg .u64 t; cvta.to.shared.u64 t, %1; cvt.u32.u64 %0, t; }" : "=r"(a) : "l"(p));
    return a;
}
#define SWZ(x) ((x) ^ (((x) >> 3) & 0x70))

__device__ __forceinline__ void cp16(uint32_t dst, const void* src) {
    asm volatile("cp.async.cg.shared.global [%0], [%1], 16;" :: "r"(dst), "l"(src) : "memory");
}
__device__ __forceinline__ void cp_commit() { asm volatile("cp.async.commit_group;" ::: "memory"); }
template<int N> __device__ __forceinline__ void cp_wait() {
    asm volatile("cp.async.wait_group %0;" :: "n"(N) : "memory");
}
__device__ __forceinline__ void ldm_x4(uint32_t& r0, uint32_t& r1, uint32_t& r2, uint32_t& r3,
                                       uint32_t addr) {
    asm volatile("ldmatrix.sync.aligned.m8n8.x4.shared.b16 {%0,%1,%2,%3}, [%4];"
                 : "=r"(r0), "=r"(r1), "=r"(r2), "=r"(r3) : "r"(addr));
}
__device__ __forceinline__ void mma16816(float* c, const uint32_t* a, uint32_t b0, uint32_t b1) {
    asm volatile(
        "mma.sync.aligned.m16n8k16.row.col.f32.bf16.bf16.f32 "
        "{%0,%1,%2,%3}, {%4,%5,%6,%7}, {%8,%9}, {%0,%1,%2,%3};"
        : "+f"(c[0]), "+f"(c[1]), "+f"(c[2]), "+f"(c[3])
        : "r"(a[0]), "r"(a[1]), "r"(a[2]), "r"(a[3]), "r"(b0), "r"(b1));
}

// ==================== dtype detection (int64 vs int32) ====================
__global__ void detect_kernel(const unsigned* __restrict__ words, int n_elems) {
    __shared__ unsigned red;
    if (threadIdx.x == 0) red = 0u;
    __syncthreads();
    int n = n_elems < 8192 ? n_elems : 8192;
    unsigned acc = 0u;
    for (int i = 1 + 2 * (int)threadIdx.x; i < n; i += 2 * (int)blockDim.x) acc |= words[i];
    if (acc) atomicOr(&red, 1u);
    __syncthreads();
    if (threadIdx.x == 0) g_is64 = (red == 0u) ? 1 : 0;
}

// ==================== embedding-bag pooling: one warp per (table, bag) ======
__global__ void pool_kernel(const void* __restrict__ idxp,
                            const void* __restrict__ offp,
                            const float* __restrict__ tables,
                            float* __restrict__ comb) {
    int wg   = (blockIdx.x * blockDim.x + threadIdx.x) >> 5;
    int lane = threadIdx.x & 31;
    if (wg >= NTAB * BATCH) return;
    int t = wg / BATCH;
    int b = wg - t * BATCH;

    const int is64 = g_is64;
    long long lo, hi;
    if (is64) {
        const long long* off = (const long long*)offp + (size_t)t * BATCH;
        lo = (b == 0) ? 0 : off[b];
        hi = (b == BATCH - 1) ? (long long)NTPER : off[b + 1];
    } else {
        const int* off = (const int*)offp + (size_t)t * BATCH;
        lo = (b == 0) ? 0 : (long long)off[b];
        hi = (b == BATCH - 1) ? (long long)NTPER : (long long)off[b + 1];
    }

    const float* tab = tables + (size_t)t * EROWS * DEMB;
    float4 acc = make_float4(0.f, 0.f, 0.f, 0.f);
    if (is64) {
        const long long* idx = (const long long*)idxp + (size_t)t * NTPER;
        for (long long i = lo; i < hi; ++i) {
            float4 v = *(const float4*)(tab + (size_t)idx[i] * DEMB + lane * 4);
            acc.x += v.x; acc.y += v.y; acc.z += v.z; acc.w += v.w;
        }
    } else {
        const int* idx = (const int*)idxp + (size_t)t * NTPER;
        for (long long i = lo; i < hi; ++i) {
            float4 v = *(const float4*)(tab + (size_t)idx[i] * DEMB + lane * 4);
            acc.x += v.x; acc.y += v.y; acc.z += v.z; acc.w += v.w;
        }
    }
    *(float4*)(comb + (size_t)b * FIN + (size_t)(t + 1) * DEMB + lane * 4) = acc;
}

// ==================== split-bf16 conversion kernels ====================
// A-layout: [h | l | h]   B-layout: [h | h | l]
__global__ void convA_kernel(const float* __restrict__ in, bf16* __restrict__ out,
                             int K, int total) {
    for (int i = blockIdx.x * blockDim.x + threadIdx.x; i < total;
         i += gridDim.x * blockDim.x) {
        int r = i / K, k = i - r * K;
        float x = in[i];
        bf16 h = __float2bfloat16(x);
        bf16 l = __float2bfloat16(x - __bfloat162float(h));
        bf16* o = out + (size_t)r * (3 * K) + k;
        o[0] = h; o[K] = l; o[2 * K] = h;
    }
}
__global__ void convB_kernel(const float* __restrict__ in, bf16* __restrict__ out,
                             int K, int total) {
    for (int i = blockIdx.x * blockDim.x + threadIdx.x; i < total;
         i += gridDim.x * blockDim.x) {
        int r = i / K, k = i - r * K;
        float x = in[i];
        bf16 h = __float2bfloat16(x);
        bf16 l = __float2bfloat16(x - __bfloat162float(h));
        bf16* o = out + (size_t)r * (3 * K) + k;
        o[0] = h; o[K] = h; o[2 * K] = l;
    }
}

// ==================== mma.sync bf16 GEMM: C = A[M,K3] * B[N,K3]^T ==========
// CTA tile 128x128, BK=64 bf16 (128B SW128 rows), 4-stage cp.async pipeline.
// 256 threads = 8 warps in 4(m) x 2(n); warp tile 32x64.
// EPI: 1 = relu(acc+bias) -> fp32 Cf
//      2 = DCN: v = comb*(acc+bias)+xlin -> fp32 Cf AND split C3
//      3 = split C3 only
//      4 = relu(acc+bias) -> split C3 only
__device__ __forceinline__ void load_stage(uint32_t base, int st, int kb,
                                           const char* Ab, const char* Bb,
                                           size_t rstride, int row_r, int c16) {
    uint32_t sA = base + (uint32_t)st * 32768u;
    uint32_t sB = sA + 16384u;
    size_t koff = (size_t)kb * 128 + c16;
#pragma unroll
    for (int j = 0; j < 4; j++) {
        int row = j * 32 + row_r;
        uint32_t so = SWZ((uint32_t)(row * 128 + c16));
        cp16(sA + so, Ab + (size_t)row * rstride + koff);
        cp16(sB + so, Bb + (size_t)row * rstride + koff);
    }
}

template<int EPI>
__global__ void __launch_bounds__(256, 1)
tc_gemm(const bf16* __restrict__ A, const bf16* __restrict__ B,
        const float* __restrict__ bias,
        float* __restrict__ Cf, int ldc,
        bf16* __restrict__ C3, int Nout, int K3,
        const float* __restrict__ comb, const float* __restrict__ xlin) {
    extern __shared__ char dsm[];
    const uint32_t base = (smem_u32(dsm) + 1023u) & ~1023u;

    const int tid  = threadIdx.x;
    const int wid  = tid >> 5, lane = tid & 31;
    const int wm   = wid & 3;        // 4 m-warps * 32 rows
    const int wn   = wid >> 2;       // 2 n-warps * 64 cols
    const int m0   = blockIdx.y * 128, n0 = blockIdx.x * 128;
    const int row_r = tid >> 3, c16 = (tid & 7) * 16;

    const char* Ab = (const char*)A + (size_t)m0 * K3 * 2;
    const char* Bb = (const char*)B + (size_t)n0 * K3 * 2;
    const size_t rstride = (size_t)K3 * 2;
    const int NKB = K3 >> 6;

    // ldmatrix lane addressing (bytes within a 128-row x 128B tile)
    const int ar = lane & 15;                 // A: row within m16 tile
    const int ac = (lane >> 4) * 16;          // A: k byte offset (0 or 16)
    const int br = lane & 7;                  // B: row within n8
    const int bn = ((lane >> 4) & 1) * 8;     // B: +8 n rows for frags 2,3
    const int bc = ((lane >> 3) & 1) * 16;    // B: +16 k bytes for frags 1,3

    float acc[2][8][4];
#pragma unroll
    for (int i = 0; i < 2; i++)
#pragma unroll
        for (int j = 0; j < 8; j++)
#pragma unroll
            for (int e = 0; e < 4; e++) acc[i][j][e] = 0.f;

    for (int s = 0; s < STAGES - 1 && s < NKB; s++) {
        load_stage(base, s, s, Ab, Bb, rstride, row_r, c16);
        cp_commit();
    }

    for (int kb = 0; kb < NKB; kb++) {
        const int st = kb % STAGES;
        cp_wait<STAGES - 2>();
        __syncthreads();

        const uint32_t sA = base + (uint32_t)st * 32768u;
        const uint32_t sB = sA + 16384u;
#pragma unroll
        for (int ks = 0; ks < 4; ks++) {
            const int kbyte = ks * 32;
            uint32_t a[2][4];
#pragma unroll
            for (int fm = 0; fm < 2; fm++) {
                uint32_t ad = sA + SWZ((uint32_t)((wm * 32 + fm * 16 + ar) * 128 + kbyte + ac));
                ldm_x4(a[fm][0], a[fm][1], a[fm][2], a[fm][3], ad);
            }
#pragma unroll
            for (int g = 0; g < 4; g++) {
                uint32_t b0, b1, b2, b3;
                uint32_t bd = sB + SWZ((uint32_t)((wn * 64 + g * 16 + bn + br) * 128 + kbyte + bc));
                ldm_x4(b0, b1, b2, b3, bd);
#pragma unroll
                for (int fm = 0; fm < 2; fm++) {
                    mma16816(acc[fm][2 * g],     a[fm], b0, b1);
                    mma16816(acc[fm][2 * g + 1], a[fm], b2, b3);
                }
            }
        }
        __syncthreads();

        const int nk = kb + STAGES - 1;
        if (nk < NKB)
            load_stage(base, nk % STAGES, nk, Ab, Bb, rstride, row_r, c16);
        cp_commit();
    }

    // ---------------- epilogue (register accumulators) ----------------
    const int er = lane >> 2;
    const int ec = (lane & 3) * 2;
#pragma unroll
    for (int fm = 0; fm < 2; fm++) {
#pragma unroll
        for (int fn = 0; fn < 8; fn++) {
            const int ng = n0 + wn * 64 + fn * 8 + ec;
#pragma unroll
            for (int rr = 0; rr < 2; rr++) {
                const int m = m0 + wm * 32 + fm * 16 + er + rr * 8;
                float v0 = acc[fm][fn][rr * 2 + 0];
                float v1 = acc[fm][fn][rr * 2 + 1];
                if (EPI == 1 || EPI == 4) {
                    v0 += bias[ng];     v0 = v0 > 0.f ? v0 : 0.f;
                    v1 += bias[ng + 1]; v1 = v1 > 0.f ? v1 : 0.f;
                }
                if (EPI == 2) {
                    size_t o = (size_t)m * ldc + ng;
                    float2 cb = *(const float2*)(comb + o);
                    float2 xb = *(const float2*)(xlin + o);
                    v0 = cb.x * (v0 + bias[ng])     + xb.x;
                    v1 = cb.y * (v1 + bias[ng + 1]) + xb.y;
                }
                if (EPI == 1 || EPI == 2)
                    *(float2*)(Cf + (size_t)m * ldc + ng) = make_float2(v0, v1);
                if (EPI >= 2) {
                    bf16 h0 = __float2bfloat16(v0);
                    bf16 l0 = __float2bfloat16(v0 - __bfloat162float(h0));
                    bf16 h1 = __float2bfloat16(v1);
                    bf16 l1 = __float2bfloat16(v1 - __bfloat162float(h1));
                    size_t o = (size_t)m * (3 * Nout) + ng;
                    __nv_bfloat162 hh; hh.x = h0; hh.y = h1;
                    __nv_bfloat162 ll; ll.x = l0; ll.y = l1;
                    *(__nv_bfloat162*)(C3 + o)            = hh;
                    *(__nv_bfloat162*)(C3 + o + Nout)     = ll;
                    *(__nv_bfloat162*)(C3 + o + 2 * Nout) = hh;
                }
            }
        }
    }
}

// ==================== fp32 fallback SGEMM (small bottom-MLP layers) ========
template<int EPI>
__global__ void __launch_bounds__(256, 2)
sgemm_nt(const float* __restrict__ A, int lda,
         const float* __restrict__ Bm, int ldb,
         const float* __restrict__ bias,
         float* __restrict__ C, int ldc, int K) {
    __shared__ __align__(16) float As[8][128];
    __shared__ __align__(16) float Bs[8][128];
    const int tid = threadIdx.x;
    const int m0 = blockIdx.y * 128, n0 = blockIdx.x * 128;
    const int lr = tid >> 1, lc = (tid & 1) * 4;
    const float* Ag = A + (size_t)(m0 + lr) * lda + lc;
    const float* Bg = Bm + (size_t)(n0 + lr) * ldb + lc;
    const int ty = tid >> 4, tx = tid & 15;

    float acc[8][8];
#pragma unroll
    for (int i = 0; i < 8; i++)
#pragma unroll
        for (int j = 0; j < 8; j++) acc[i][j] = 0.f;

    for (int k0 = 0; k0 < K; k0 += 8) {
#pragma unroll
        for (int j = 0; j < 4; j++) {
            int kk = k0 + lc + j;
            As[lc + j][lr] = (kk < K) ? Ag[k0 + j] : 0.f;
            Bs[lc + j][lr] = (kk < K) ? Bg[k0 + j] : 0.f;
        }
        __syncthreads();
#pragma unroll
        for (int k = 0; k < 8; k++) {
            float4 a0 = *(const float4*)&As[k][ty * 4];
            float4 a1 = *(const float4*)&As[k][64 + ty * 4];
            float4 b0 = *(const float4*)&Bs[k][tx * 4];
            float4 b1 = *(const float4*)&Bs[k][64 + tx * 4];
            float af[8] = {a0.x, a0.y, a0.z, a0.w, a1.x, a1.y, a1.z, a1.w};
            float bf[8] = {b0.x, b0.y, b0.z, b0.w, b1.x, b1.y, b1.z, b1.w};
#pragma unroll
            for (int i = 0; i < 8; i++)
#pragma unroll
                for (int j = 0; j < 8; j++) acc[i][j] += af[i] * bf[j];
        }
        __syncthreads();
    }
#pragma unroll
    for (int i = 0; i < 8; i++) {
        int mg = m0 + ((i < 4) ? (ty * 4 + i) : (64 + ty * 4 + (i - 4)));
        size_t rowoff = (size_t)mg * ldc;
#pragma unroll
        for (int j = 0; j < 8; j++) {
            int ng = n0 + ((j < 4) ? (tx * 4 + j) : (64 + tx * 4 + (j - 4)));
            float v = acc[i][j];
            if (EPI == 1) { v += bias[ng]; v = v > 0.f ? v : 0.f; }
            C[rowoff + ng] = v;
        }
    }
}

// ==================== final layer ====================
__global__ void final_kernel(const float* __restrict__ z, const float* __restrict__ w,
                             const float* __restrict__ b3, float* __restrict__ out) {
    int row = blockIdx.x;
    float s = 0.f;
    for (int j = threadIdx.x; j < 512; j += 128)
        s += z[(size_t)row * 512 + j] * w[j];
#pragma unroll
    for (int o = 16; o > 0; o >>= 1) s += __shfl_down_sync(0xffffffffu, s, o);
    __shared__ float sm[4];
    if ((threadIdx.x & 31) == 0) sm[threadIdx.x >> 5] = s;
    __syncthreads();
    if (threadIdx.x == 0) out[row] = sm[0] + sm[1] + sm[2] + sm[3] + b3[0];
}

// ==================== launch ====================
extern "C" void kernel_launch(void* const* d_in, const int* in_sizes, int n_in,
                              void* d_out, int out_size) {
    const float* dense   = (const float*)d_in[0];
    const void*  indices = d_in[1];
    const void*  offsets = d_in[2];
    const float* emb     = (const float*)d_in[3];
    const float* bW0 = (const float*)d_in[4];  const float* bb0 = (const float*)d_in[5];
    const float* bW1 = (const float*)d_in[6];  const float* bb1 = (const float*)d_in[7];
    const float* bW2 = (const float*)d_in[8];  const float* bb2 = (const float*)d_in[9];
    const float* dcnW = (const float*)d_in[10];
    const float* dcnV = (const float*)d_in[11];
    const float* dcnb = (const float*)d_in[12];
    const float* tW0 = (const float*)d_in[13]; const float* tb0 = (const float*)d_in[14];
    const float* tW1 = (const float*)d_in[15]; const float* tb1 = (const float*)d_in[16];
    const float* tW2 = (const float*)d_in[17]; const float* tb2 = (const float*)d_in[18];
    const float* tW3 = (const float*)d_in[19]; const float* tb3 = (const float*)d_in[20];

    float *bot0, *bot1, *comb, *xl, *z2;
    bf16 *act3, *act3b, *xv3, *wb3;
    cudaGetSymbolAddress((void**)&bot0, g_bot0);
    cudaGetSymbolAddress((void**)&bot1, g_bot1);
    cudaGetSymbolAddress((void**)&comb, g_comb);
    cudaGetSymbolAddress((void**)&xl,   g_xl);
    cudaGetSymbolAddress((void**)&z2,   g_z2);
    cudaGetSymbolAddress((void**)&act3,  g_act3);
    cudaGetSymbolAddress((void**)&act3b, g_act3b);
    cudaGetSymbolAddress((void**)&xv3,   g_xv3);
    cudaGetSymbolAddress((void**)&wb3,   g_wb3);

    const int dynsmem = STAGES * 32768 + 1024;
    cudaFuncSetAttribute(tc_gemm<1>, cudaFuncAttributeMaxDynamicSharedMemorySize, dynsmem);
    cudaFuncSetAttribute(tc_gemm<2>, cudaFuncAttributeMaxDynamicSharedMemorySize, dynsmem);
    cudaFuncSetAttribute(tc_gemm<3>, cudaFuncAttributeMaxDynamicSharedMemorySize, dynsmem);
    cudaFuncSetAttribute(tc_gemm<4>, cudaFuncAttributeMaxDynamicSharedMemorySize, dynsmem);

    // --- bottom MLP: 13 -> 512 -> 256 -> 128 (relu), last into comb slot 0
    sgemm_nt<1><<<dim3(4, 32), 256>>>(dense, 13,  bW0, 13,  bb0, bot0, 512, 13);
    sgemm_nt<1><<<dim3(2, 32), 256>>>(bot0, 512,  bW1, 512, bb1, bot1, 256, 512);
    sgemm_nt<1><<<dim3(1, 32), 256>>>(bot1, 256,  bW2, 256, bb2, comb, FIN, 256);

    // --- embedding-bag pooling into comb slots 1..26
    detect_kernel<<<1, 256>>>((const unsigned*)offsets, in_sizes[2]);
    pool_kernel<<<(NTAB * BATCH) / 8, 256>>>(indices, offsets, emb, comb);

    // --- split comb -> act3 (A layout)
    convA_kernel<<<2048, 256>>>(comb, act3, FIN, BATCH * FIN);

    // --- low-rank DCN (tensor cores, split-bf16, K' = 3K)
    for (int l = 0; l < 3; l++) {
        convB_kernel<<<2048, 256>>>(dcnV + (size_t)l * LOWR * FIN, wb3, FIN, LOWR * FIN);
        tc_gemm<3><<<dim3(LOWR / 128, 32), 256, dynsmem>>>(
            act3, wb3, nullptr, nullptr, 0, xv3, LOWR, 3 * FIN, nullptr, nullptr);

        convB_kernel<<<2048, 256>>>(dcnW + (size_t)l * FIN * LOWR, wb3, LOWR, FIN * LOWR);
        tc_gemm<2><<<dim3(FIN / 128, 32), 256, dynsmem>>>(
            xv3, wb3, dcnb + (size_t)l * FIN, xl, FIN, act3, FIN, 3 * LOWR,
            comb, (l == 0) ? comb : xl);
    }

    // --- top MLP: 3456 -> 1024 -> 1024 -> 512 (relu) -> 1
    convB_kernel<<<2048, 256>>>(tW0, wb3, FIN, 1024 * FIN);
    tc_gemm<4><<<dim3(8, 32), 256, dynsmem>>>(
        act3, wb3, tb0, nullptr, 0, act3b, 1024, 3 * FIN, nullptr, nullptr);

    convB_kernel<<<2048, 256>>>(tW1, wb3, 1024, 1024 * 1024);
    tc_gemm<4><<<dim3(8, 32), 256, dynsmem>>>(
        act3b, wb3, tb1, nullptr, 0, act3, 1024, 3 * 1024, nullptr, nullptr);

    convB_kernel<<<2048, 256>>>(tW2, wb3, 1024, 512 * 1024);
    tc_gemm<1><<<dim3(4, 32), 256, dynsmem>>>(
        act3, wb3, tb2, z2, 512, nullptr, 0, 3 * 1024, nullptr, nullptr);

    final_kernel<<<BATCH, 128>>>(z2, tW3, tb3, (float*)d_out);
}

// round 8
// speedup vs baseline: 3.0515x; 1.0288x over previous
#include <cuda_runtime.h>
#include <cuda_bf16.h>
#include <cstdint>
#include <cstddef>

typedef __nv_bfloat16 bf16;

// ---------------- problem constants ----------------
#define BATCH   4096
#define NTAB    26
#define DEMB    128
#define NTPER   81920
#define EROWS   100000
#define FIN     3456
#define LOWR    512
#define STAGES  3

// ---------------- scratch (device globals; no runtime alloc) ----------------
__device__ float g_bot0[BATCH * 512];
__device__ float g_bot1[BATCH * 256];
__device__ float g_comb[BATCH * FIN];        // combined features (fp32, immutable)
__device__ float g_z2  [BATCH * 512];
__device__ int   g_is64;
__device__ bf16  g_act3 [BATCH * 3 * FIN];   // split activations (comb -> xl evolving)
__device__ bf16  g_act3b[BATCH * 3 * 1024];  // split z0/z1 ping
__device__ bf16  g_act3c[BATCH * 3 * 1024];  // split z1 pong
__device__ bf16  g_xv3  [BATCH * 3 * LOWR];  // split xv
__device__ bf16  g_wb3  [1024 * 3 * FIN];    // shared split-weight scratch (max tW0)

// ==================== PTX helpers ====================
__device__ __forceinline__ uint32_t smem_u32(const void* p) {
    uint32_t a;
    asm("{ .reg .u64 t; cvta.to.shared.u64 t, %1; cvt.u32.u64 %0, t; }" : "=r"(a) : "l"(p));
    return a;
}
#define SWZ(x) ((x) ^ (((x) >> 3) & 0x70))

__device__ __forceinline__ void cp16(uint32_t dst, const void* src) {
    asm volatile("cp.async.cg.shared.global [%0], [%1], 16;" :: "r"(dst), "l"(src) : "memory");
}
__device__ __forceinline__ void cp_commit() { asm volatile("cp.async.commit_group;" ::: "memory"); }
template<int N> __device__ __forceinline__ void cp_wait() {
    asm volatile("cp.async.wait_group %0;" :: "n"(N) : "memory");
}
__device__ __forceinline__ void ldm_x4(uint32_t& r0, uint32_t& r1, uint32_t& r2, uint32_t& r3,
                                       uint32_t addr) {
    asm volatile("ldmatrix.sync.aligned.m8n8.x4.shared.b16 {%0,%1,%2,%3}, [%4];"
                 : "=r"(r0), "=r"(r1), "=r"(r2), "=r"(r3) : "r"(addr));
}
__device__ __forceinline__ void mma16816(float* c, const uint32_t* a, uint32_t b0, uint32_t b1) {
    asm volatile(
        "mma.sync.aligned.m16n8k16.row.col.f32.bf16.bf16.f32 "
        "{%0,%1,%2,%3}, {%4,%5,%6,%7}, {%8,%9}, {%0,%1,%2,%3};"
        : "+f"(c[0]), "+f"(c[1]), "+f"(c[2]), "+f"(c[3])
        : "r"(a[0]), "r"(a[1]), "r"(a[2]), "r"(a[3]), "r"(b0), "r"(b1));
}

// ==================== dtype detection (int64 vs int32) ====================
__global__ void detect_kernel(const unsigned* __restrict__ words, int n_elems) {
    __shared__ unsigned red;
    if (threadIdx.x == 0) red = 0u;
    __syncthreads();
    int n = n_elems < 8192 ? n_elems : 8192;
    unsigned acc = 0u;
    for (int i = 1 + 2 * (int)threadIdx.x; i < n; i += 2 * (int)blockDim.x) acc |= words[i];
    if (acc) atomicOr(&red, 1u);
    __syncthreads();
    if (threadIdx.x == 0) g_is64 = (red == 0u) ? 1 : 0;
}

// ==================== embedding-bag pooling: one warp per (table, bag) ======
// Also fuses the split-bf16 conversion of the pooled row into act3.
template<typename IT>
__device__ __forceinline__ float4 pool_rows(const IT* __restrict__ idx,
                                            const float* __restrict__ tab,
                                            long long lo, long long hi, int lane) {
    float4 acc = make_float4(0.f, 0.f, 0.f, 0.f);
    long long i = lo;
    for (; i + 4 <= hi; i += 4) {
        size_t r0 = (size_t)idx[i],     r1 = (size_t)idx[i + 1];
        size_t r2 = (size_t)idx[i + 2], r3 = (size_t)idx[i + 3];
        float4 v0 = *(const float4*)(tab + r0 * DEMB + lane * 4);
        float4 v1 = *(const float4*)(tab + r1 * DEMB + lane * 4);
        float4 v2 = *(const float4*)(tab + r2 * DEMB + lane * 4);
        float4 v3 = *(const float4*)(tab + r3 * DEMB + lane * 4);
        acc.x += v0.x + v1.x + v2.x + v3.x;
        acc.y += v0.y + v1.y + v2.y + v3.y;
        acc.z += v0.z + v1.z + v2.z + v3.z;
        acc.w += v0.w + v1.w + v2.w + v3.w;
    }
    for (; i < hi; ++i) {
        float4 v = *(const float4*)(tab + (size_t)idx[i] * DEMB + lane * 4);
        acc.x += v.x; acc.y += v.y; acc.z += v.z; acc.w += v.w;
    }
    return acc;
}

__device__ __forceinline__ void split_store2(bf16* __restrict__ a3, size_t o, int Nout,
                                             float v0, float v1) {
    bf16 h0 = __float2bfloat16(v0);
    bf16 l0 = __float2bfloat16(v0 - __bfloat162float(h0));
    bf16 h1 = __float2bfloat16(v1);
    bf16 l1 = __float2bfloat16(v1 - __bfloat162float(h1));
    __nv_bfloat162 hh; hh.x = h0; hh.y = h1;
    __nv_bfloat162 ll; ll.x = l0; ll.y = l1;
    *(__nv_bfloat162*)(a3 + o)            = hh;
    *(__nv_bfloat162*)(a3 + o + Nout)     = ll;
    *(__nv_bfloat162*)(a3 + o + 2 * Nout) = hh;
}

__global__ void pool_kernel(const void* __restrict__ idxp,
                            const void* __restrict__ offp,
                            const float* __restrict__ tables,
                            float* __restrict__ comb,
                            bf16* __restrict__ act3) {
    int wg   = (blockIdx.x * blockDim.x + threadIdx.x) >> 5;
    int lane = threadIdx.x & 31;
    if (wg >= NTAB * BATCH) return;
    int t = wg / BATCH;
    int b = wg - t * BATCH;

    const int is64 = g_is64;
    long long lo, hi;
    if (is64) {
        const long long* off = (const long long*)offp + (size_t)t * BATCH;
        lo = (b == 0) ? 0 : off[b];
        hi = (b == BATCH - 1) ? (long long)NTPER : off[b + 1];
    } else {
        const int* off = (const int*)offp + (size_t)t * BATCH;
        lo = (b == 0) ? 0 : (long long)off[b];
        hi = (b == BATCH - 1) ? (long long)NTPER : (long long)off[b + 1];
    }

    const float* tab = tables + (size_t)t * EROWS * DEMB;
    float4 acc;
    if (is64) acc = pool_rows((const long long*)idxp + (size_t)t * NTPER, tab, lo, hi, lane);
    else      acc = pool_rows((const int*)idxp + (size_t)t * NTPER, tab, lo, hi, lane);

    const int col = (t + 1) * DEMB + lane * 4;
    *(float4*)(comb + (size_t)b * FIN + col) = acc;
    size_t o = (size_t)b * (3 * FIN) + col;
    split_store2(act3, o,     FIN, acc.x, acc.y);
    split_store2(act3, o + 2, FIN, acc.z, acc.w);
}

// ==================== split-bf16 weight conversion (B layout [h|h|l]) ======
__global__ void convB_kernel(const float* __restrict__ in, bf16* __restrict__ out,
                             int K, int total) {
    for (int i = blockIdx.x * blockDim.x + threadIdx.x; i < total;
         i += gridDim.x * blockDim.x) {
        int r = i / K, k = i - r * K;
        float x = in[i];
        bf16 h = __float2bfloat16(x);
        bf16 l = __float2bfloat16(x - __bfloat162float(h));
        bf16* o = out + (size_t)r * (3 * K) + k;
        o[0] = h; o[K] = h; o[2 * K] = l;
    }
}

// ==================== mma.sync bf16 GEMM: C = A[M,K3] * B[N,K3]^T ==========
// CTA tile 128x128, BK=64 bf16 (128B SW128 rows), 3-stage cp.async pipeline,
// 2 CTAs/SM. 256 threads = 8 warps 4(m) x 2(n); warp tile 32x64.
// EPI: 1 = relu(acc+bias) -> fp32 Cf
//      2 = DCN: xlin = h+l from old C3; v = comb*(acc+bias)+xlin -> split C3
//      3 = split C3 only
//      4 = relu(acc+bias) -> split C3 only
__device__ __forceinline__ void load_stage(uint32_t base, int st, int kb,
                                           const char* Ab, const char* Bb,
                                           size_t rstride, int row_r, int c16) {
    uint32_t sA = base + (uint32_t)st * 32768u;
    uint32_t sB = sA + 16384u;
    size_t koff = (size_t)kb * 128 + c16;
#pragma unroll
    for (int j = 0; j < 4; j++) {
        int row = j * 32 + row_r;
        uint32_t so = SWZ((uint32_t)(row * 128 + c16));
        cp16(sA + so, Ab + (size_t)row * rstride + koff);
        cp16(sB + so, Bb + (size_t)row * rstride + koff);
    }
}

template<int EPI>
__global__ void __launch_bounds__(256, 2)
tc_gemm(const bf16* __restrict__ A, const bf16* __restrict__ B,
        const float* __restrict__ bias,
        float* __restrict__ Cf, int ldc,
        bf16* __restrict__ C3, int Nout, int K3,
        const float* __restrict__ comb) {
    extern __shared__ char dsm[];
    const uint32_t base = (smem_u32(dsm) + 1023u) & ~1023u;

    const int tid  = threadIdx.x;
    const int wid  = tid >> 5, lane = tid & 31;
    const int wm   = wid & 3;
    const int wn   = wid >> 2;
    const int m0   = blockIdx.y * 128, n0 = blockIdx.x * 128;
    const int row_r = tid >> 3, c16 = (tid & 7) * 16;

    const char* Ab = (const char*)A + (size_t)m0 * K3 * 2;
    const char* Bb = (const char*)B + (size_t)n0 * K3 * 2;
    const size_t rstride = (size_t)K3 * 2;
    const int NKB = K3 >> 6;

    const int ar = lane & 15;
    const int ac = (lane >> 4) * 16;
    const int br = lane & 7;
    const int bn = ((lane >> 4) & 1) * 8;
    const int bc = ((lane >> 3) & 1) * 16;

    float acc[2][8][4];
#pragma unroll
    for (int i = 0; i < 2; i++)
#pragma unroll
        for (int j = 0; j < 8; j++)
#pragma unroll
            for (int e = 0; e < 4; e++) acc[i][j][e] = 0.f;

    for (int s = 0; s < STAGES - 1 && s < NKB; s++) {
        load_stage(base, s, s, Ab, Bb, rstride, row_r, c16);
        cp_commit();
    }

    for (int kb = 0; kb < NKB; kb++) {
        const int st = kb % STAGES;
        cp_wait<STAGES - 2>();
        __syncthreads();

        const uint32_t sA = base + (uint32_t)st * 32768u;
        const uint32_t sB = sA + 16384u;
#pragma unroll
        for (int ks = 0; ks < 4; ks++) {
            const int kbyte = ks * 32;
            uint32_t a[2][4];
#pragma unroll
            for (int fm = 0; fm < 2; fm++) {
                uint32_t ad = sA + SWZ((uint32_t)((wm * 32 + fm * 16 + ar) * 128 + kbyte + ac));
                ldm_x4(a[fm][0], a[fm][1], a[fm][2], a[fm][3], ad);
            }
#pragma unroll
            for (int g = 0; g < 4; g++) {
                uint32_t b0, b1, b2, b3;
                uint32_t bd = sB + SWZ((uint32_t)((wn * 64 + g * 16 + bn + br) * 128 + kbyte + bc));
                ldm_x4(b0, b1, b2, b3, bd);
#pragma unroll
                for (int fm = 0; fm < 2; fm++) {
                    mma16816(acc[fm][2 * g],     a[fm], b0, b1);
                    mma16816(acc[fm][2 * g + 1], a[fm], b2, b3);
                }
            }
        }
        // NOTE: the slot refilled below ((kb-1)%STAGES) was consumed at iter kb-1,
        // already fenced by this iteration's post-wait __syncthreads().
        const int nk = kb + STAGES - 1;
        if (nk < NKB)
            load_stage(base, nk % STAGES, nk, Ab, Bb, rstride, row_r, c16);
        cp_commit();
    }

    // ---------------- epilogue (register accumulators) ----------------
    const int er = lane >> 2;
    const int ec = (lane & 3) * 2;
#pragma unroll
    for (int fm = 0; fm < 2; fm++) {
#pragma unroll
        for (int fn = 0; fn < 8; fn++) {
            const int ng = n0 + wn * 64 + fn * 8 + ec;
#pragma unroll
            for (int rr = 0; rr < 2; rr++) {
                const int m = m0 + wm * 32 + fm * 16 + er + rr * 8;
                float v0 = acc[fm][fn][rr * 2 + 0];
                float v1 = acc[fm][fn][rr * 2 + 1];
                if (EPI == 1 || EPI == 4) {
                    v0 += bias[ng];     v0 = v0 > 0.f ? v0 : 0.f;
                    v1 += bias[ng + 1]; v1 = v1 > 0.f ? v1 : 0.f;
                }
                if (EPI == 2) {
                    size_t o3 = (size_t)m * (3 * Nout) + ng;
                    __nv_bfloat162 oh = *(const __nv_bfloat162*)(C3 + o3);
                    __nv_bfloat162 ol = *(const __nv_bfloat162*)(C3 + o3 + Nout);
                    float x0 = __bfloat162float(oh.x) + __bfloat162float(ol.x);
                    float x1 = __bfloat162float(oh.y) + __bfloat162float(ol.y);
                    float2 cb = *(const float2*)(comb + (size_t)m * ldc + ng);
                    v0 = cb.x * (v0 + bias[ng])     + x0;
                    v1 = cb.y * (v1 + bias[ng + 1]) + x1;
                }
                if (EPI == 1)
                    *(float2*)(Cf + (size_t)m * ldc + ng) = make_float2(v0, v1);
                if (EPI >= 2)
                    split_store2(C3, (size_t)m * (3 * Nout) + ng, Nout, v0, v1);
            }
        }
    }
}

// ==================== fp32 SGEMM (small bottom-MLP layers) =================
// EPI: 1 = relu -> fp32 C.   5 = relu -> fp32 C AND split C3 (A layout).
template<int EPI>
__global__ void __launch_bounds__(256, 2)
sgemm_nt(const float* __restrict__ A, int lda,
         const float* __restrict__ Bm, int ldb,
         const float* __restrict__ bias,
         float* __restrict__ C, int ldc, int K,
         bf16* __restrict__ C3, int Nout) {
    __shared__ __align__(16) float As[8][128];
    __shared__ __align__(16) float Bs[8][128];
    const int tid = threadIdx.x;
    const int m0 = blockIdx.y * 128, n0 = blockIdx.x * 128;
    const int lr = tid >> 1, lc = (tid & 1) * 4;
    const float* Ag = A + (size_t)(m0 + lr) * lda + lc;
    const float* Bg = Bm + (size_t)(n0 + lr) * ldb + lc;
    const int ty = tid >> 4, tx = tid & 15;

    float acc[8][8];
#pragma unroll
    for (int i = 0; i < 8; i++)
#pragma unroll
        for (int j = 0; j < 8; j++) acc[i][j] = 0.f;

    for (int k0 = 0; k0 < K; k0 += 8) {
#pragma unroll
        for (int j = 0; j < 4; j++) {
            int kk = k0 + lc + j;
            As[lc + j][lr] = (kk < K) ? Ag[k0 + j] : 0.f;
            Bs[lc + j][lr] = (kk < K) ? Bg[k0 + j] : 0.f;
        }
        __syncthreads();
#pragma unroll
        for (int k = 0; k < 8; k++) {
            float4 a0 = *(const float4*)&As[k][ty * 4];
            float4 a1 = *(const float4*)&As[k][64 + ty * 4];
            float4 b0 = *(const float4*)&Bs[k][tx * 4];
            float4 b1 = *(const float4*)&Bs[k][64 + tx * 4];
            float af[8] = {a0.x, a0.y, a0.z, a0.w, a1.x, a1.y, a1.z, a1.w};
            float bf[8] = {b0.x, b0.y, b0.z, b0.w, b1.x, b1.y, b1.z, b1.w};
#pragma unroll
            for (int i = 0; i < 8; i++)
#pragma unroll
                for (int j = 0; j < 8; j++) acc[i][j] += af[i] * bf[j];
        }
        __syncthreads();
    }
#pragma unroll
    for (int i = 0; i < 8; i++) {
        int mg = m0 + ((i < 4) ? (ty * 4 + i) : (64 + ty * 4 + (i - 4)));
        size_t rowoff = (size_t)mg * ldc;
#pragma unroll
        for (int j = 0; j < 8; j++) {
            int ng = n0 + ((j < 4) ? (tx * 4 + j) : (64 + tx * 4 + (j - 4)));
            float v = acc[i][j] + bias[ng];
            v = v > 0.f ? v : 0.f;
            C[rowoff + ng] = v;
            if (EPI == 5) {
                bf16 h = __float2bfloat16(v);
                bf16 l = __float2bfloat16(v - __bfloat162float(h));
                size_t o = (size_t)mg * (3 * Nout) + ng;
                C3[o] = h; C3[o + Nout] = l; C3[o + 2 * Nout] = h;
            }
        }
    }
}

// ==================== final layer ====================
__global__ void final_kernel(const float* __restrict__ z, const float* __restrict__ w,
                             const float* __restrict__ b3, float* __restrict__ out) {
    int row = blockIdx.x;
    float s = 0.f;
    for (int j = threadIdx.x; j < 512; j += 128)
        s += z[(size_t)row * 512 + j] * w[j];
#pragma unroll
    for (int o = 16; o > 0; o >>= 1) s += __shfl_down_sync(0xffffffffu, s, o);
    __shared__ float sm[4];
    if ((threadIdx.x & 31) == 0) sm[threadIdx.x >> 5] = s;
    __syncthreads();
    if (threadIdx.x == 0) out[row] = sm[0] + sm[1] + sm[2] + sm[3] + b3[0];
}

// ==================== launch ====================
extern "C" void kernel_launch(void* const* d_in, const int* in_sizes, int n_in,
                              void* d_out, int out_size) {
    const float* dense   = (const float*)d_in[0];
    const void*  indices = d_in[1];
    const void*  offsets = d_in[2];
    const float* emb     = (const float*)d_in[3];
    const float* bW0 = (const float*)d_in[4];  const float* bb0 = (const float*)d_in[5];
    const float* bW1 = (const float*)d_in[6];  const float* bb1 = (const float*)d_in[7];
    const float* bW2 = (const float*)d_in[8];  const float* bb2 = (const float*)d_in[9];
    const float* dcnW = (const float*)d_in[10];
    const float* dcnV = (const float*)d_in[11];
    const float* dcnb = (const float*)d_in[12];
    const float* tW0 = (const float*)d_in[13]; const float* tb0 = (const float*)d_in[14];
    const float* tW1 = (const float*)d_in[15]; const float* tb1 = (const float*)d_in[16];
    const float* tW2 = (const float*)d_in[17]; const float* tb2 = (const float*)d_in[18];
    const float* tW3 = (const float*)d_in[19]; const float* tb3 = (const float*)d_in[20];

    float *bot0, *bot1, *comb, *z2;
    bf16 *act3, *act3b, *act3c, *xv3, *wb3;
    cudaGetSymbolAddress((void**)&bot0, g_bot0);
    cudaGetSymbolAddress((void**)&bot1, g_bot1);
    cudaGetSymbolAddress((void**)&comb, g_comb);
    cudaGetSymbolAddress((void**)&z2,   g_z2);
    cudaGetSymbolAddress((void**)&act3,  g_act3);
    cudaGetSymbolAddress((void**)&act3b, g_act3b);
    cudaGetSymbolAddress((void**)&act3c, g_act3c);
    cudaGetSymbolAddress((void**)&xv3,   g_xv3);
    cudaGetSymbolAddress((void**)&wb3,   g_wb3);

    const int dynsmem = STAGES * 32768 + 1024;
    cudaFuncSetAttribute(tc_gemm<1>, cudaFuncAttributeMaxDynamicSharedMemorySize, dynsmem);
    cudaFuncSetAttribute(tc_gemm<2>, cudaFuncAttributeMaxDynamicSharedMemorySize, dynsmem);
    cudaFuncSetAttribute(tc_gemm<3>, cudaFuncAttributeMaxDynamicSharedMemorySize, dynsmem);
    cudaFuncSetAttribute(tc_gemm<4>, cudaFuncAttributeMaxDynamicSharedMemorySize, dynsmem);

    // --- bottom MLP: 13 -> 512 -> 256 -> 128 (relu); layer 3 writes comb + act3 slot 0
    sgemm_nt<1><<<dim3(4, 32), 256>>>(dense, 13,  bW0, 13,  bb0, bot0, 512, 13,  nullptr, 0);
    sgemm_nt<1><<<dim3(2, 32), 256>>>(bot0, 512,  bW1, 512, bb1, bot1, 256, 512, nullptr, 0);
    sgemm_nt<5><<<dim3(1, 32), 256>>>(bot1, 256,  bW2, 256, bb2, comb, FIN, 256, act3, FIN);

    // --- embedding-bag pooling into comb + act3 slots 1..26
    detect_kernel<<<1, 256>>>((const unsigned*)offsets, in_sizes[2]);
    pool_kernel<<<(NTAB * BATCH) / 8, 256>>>(indices, offsets, emb, comb, act3);

    // --- low-rank DCN (tensor cores, split-bf16, K' = 3K); x_l lives in act3
    for (int l = 0; l < 3; l++) {
        convB_kernel<<<2048, 256>>>(dcnV + (size_t)l * LOWR * FIN, wb3, FIN, LOWR * FIN);
        tc_gemm<3><<<dim3(LOWR / 128, 32), 256, dynsmem>>>(
            act3, wb3, nullptr, nullptr, 0, xv3, LOWR, 3 * FIN, nullptr);

        convB_kernel<<<2048, 256>>>(dcnW + (size_t)l * FIN * LOWR, wb3, LOWR, FIN * LOWR);
        tc_gemm<2><<<dim3(FIN / 128, 32), 256, dynsmem>>>(
            xv3, wb3, dcnb + (size_t)l * FIN, nullptr, FIN, act3, FIN, 3 * LOWR, comb);
    }

    // --- top MLP: 3456 -> 1024 -> 1024 -> 512 (relu) -> 1
    convB_kernel<<<2048, 256>>>(tW0, wb3, FIN, 1024 * FIN);
    tc_gemm<4><<<dim3(8, 32), 256, dynsmem>>>(
        act3, wb3, tb0, nullptr, 0, act3b, 1024, 3 * FIN, nullptr);

    convB_kernel<<<2048, 256>>>(tW1, wb3, 1024, 1024 * 1024);
    tc_gemm<4><<<dim3(8, 32), 256, dynsmem>>>(
        act3b, wb3, tb1, nullptr, 0, act3c, 1024, 3 * 1024, nullptr);

    convB_kernel<<<2048, 256>>>(tW2, wb3, 1024, 512 * 1024);
    tc_gemm<1><<<dim3(4, 32), 256, dynsmem>>>(
        act3c, wb3, tb2, z2, 512, nullptr, 0, 3 * 1024, nullptr);

    final_kernel<<<BATCH, 128>>>(z2, tW3, tb3, (float*)d_out);
}

// round 9
// speedup vs baseline: 4.1427x; 1.3576x over previous
#include <cuda_runtime.h>
#include <cuda_fp16.h>
#include <cstdint>
#include <cstddef>

// ---------------- problem constants ----------------
#define BATCH   4096
#define NTAB    26
#define DEMB    128
#define NTPER   81920
#define EROWS   100000
#define FIN     3456
#define LOWR    512
#define STAGES  3

// ---------------- scratch (device globals; no runtime alloc) ----------------
__device__ float  g_bot0[BATCH * 512];
__device__ float  g_bot1[BATCH * 256];
__device__ float  g_comb[BATCH * FIN];        // combined features (fp32, immutable)
__device__ float  g_z2  [BATCH * 512];
__device__ int    g_is64;
__device__ __half g_act2 [BATCH * 2 * FIN];   // split activations [h|l] (comb -> xl)
__device__ __half g_act2b[BATCH * 2 * 1024];  // split z0
__device__ __half g_act2c[BATCH * 2 * 1024];  // split z1
__device__ __half g_xv2  [BATCH * 2 * LOWR];  // split xv
__device__ __half g_wb   [1024 * FIN];        // fp16 weight scratch (max tW0)

// ==================== PTX helpers ====================
__device__ __forceinline__ uint32_t smem_u32(const void* p) {
    uint32_t a;
    asm("{ .reg .u64 t; cvta.to.shared.u64 t, %1; cvt.u32.u64 %0, t; }" : "=r"(a) : "l"(p));
    return a;
}
#define SWZ(x) ((x) ^ (((x) >> 3) & 0x70))

__device__ __forceinline__ void cp16(uint32_t dst, const void* src) {
    asm volatile("cp.async.cg.shared.global [%0], [%1], 16;" :: "r"(dst), "l"(src) : "memory");
}
__device__ __forceinline__ void cp_commit() { asm volatile("cp.async.commit_group;" ::: "memory"); }
template<int N> __device__ __forceinline__ void cp_wait() {
    asm volatile("cp.async.wait_group %0;" :: "n"(N) : "memory");
}
__device__ __forceinline__ void ldm_x4(uint32_t& r0, uint32_t& r1, uint32_t& r2, uint32_t& r3,
                                       uint32_t addr) {
    asm volatile("ldmatrix.sync.aligned.m8n8.x4.shared.b16 {%0,%1,%2,%3}, [%4];"
                 : "=r"(r0), "=r"(r1), "=r"(r2), "=r"(r3) : "r"(addr));
}
__device__ __forceinline__ void mma16816(float* c, const uint32_t* a, uint32_t b0, uint32_t b1) {
    asm volatile(
        "mma.sync.aligned.m16n8k16.row.col.f32.f16.f16.f32 "
        "{%0,%1,%2,%3}, {%4,%5,%6,%7}, {%8,%9}, {%0,%1,%2,%3};"
        : "+f"(c[0]), "+f"(c[1]), "+f"(c[2]), "+f"(c[3])
        : "r"(a[0]), "r"(a[1]), "r"(a[2]), "r"(a[3]), "r"(b0), "r"(b1));
}

// split store: h at o, l at o+Nout (pairs, half2)
__device__ __forceinline__ void split_store2(__half* __restrict__ a2, size_t o, int Nout,
                                             float v0, float v1) {
    __half h0 = __float2half_rn(v0);
    __half l0 = __float2half_rn(v0 - __half2float(h0));
    __half h1 = __float2half_rn(v1);
    __half l1 = __float2half_rn(v1 - __half2float(h1));
    __half2 hh; hh.x = h0; hh.y = h1;
    __half2 ll; ll.x = l0; ll.y = l1;
    *(__half2*)(a2 + o)        = hh;
    *(__half2*)(a2 + o + Nout) = ll;
}

// ==================== dtype detection (int64 vs int32) ====================
__global__ void detect_kernel(const unsigned* __restrict__ words, int n_elems) {
    __shared__ unsigned red;
    if (threadIdx.x == 0) red = 0u;
    __syncthreads();
    int n = n_elems < 8192 ? n_elems : 8192;
    unsigned acc = 0u;
    for (int i = 1 + 2 * (int)threadIdx.x; i < n; i += 2 * (int)blockDim.x) acc |= words[i];
    if (acc) atomicOr(&red, 1u);
    __syncthreads();
    if (threadIdx.x == 0) g_is64 = (red == 0u) ? 1 : 0;
}

// ==================== embedding-bag pooling: one warp per (table, bag) ======
template<typename IT>
__device__ __forceinline__ float4 pool_rows(const IT* __restrict__ idx,
                                            const float* __restrict__ tab,
                                            long long lo, long long hi, int lane) {
    float4 acc = make_float4(0.f, 0.f, 0.f, 0.f);
    long long i = lo;
    for (; i + 4 <= hi; i += 4) {
        size_t r0 = (size_t)idx[i],     r1 = (size_t)idx[i + 1];
        size_t r2 = (size_t)idx[i + 2], r3 = (size_t)idx[i + 3];
        float4 v0 = *(const float4*)(tab + r0 * DEMB + lane * 4);
        float4 v1 = *(const float4*)(tab + r1 * DEMB + lane * 4);
        float4 v2 = *(const float4*)(tab + r2 * DEMB + lane * 4);
        float4 v3 = *(const float4*)(tab + r3 * DEMB + lane * 4);
        acc.x += v0.x + v1.x + v2.x + v3.x;
        acc.y += v0.y + v1.y + v2.y + v3.y;
        acc.z += v0.z + v1.z + v2.z + v3.z;
        acc.w += v0.w + v1.w + v2.w + v3.w;
    }
    for (; i < hi; ++i) {
        float4 v = *(const float4*)(tab + (size_t)idx[i] * DEMB + lane * 4);
        acc.x += v.x; acc.y += v.y; acc.z += v.z; acc.w += v.w;
    }
    return acc;
}

__global__ void pool_kernel(const void* __restrict__ idxp,
                            const void* __restrict__ offp,
                            const float* __restrict__ tables,
                            float* __restrict__ comb,
                            __half* __restrict__ act2) {
    int wg   = (blockIdx.x * blockDim.x + threadIdx.x) >> 5;
    int lane = threadIdx.x & 31;
    if (wg >= NTAB * BATCH) return;
    int t = wg / BATCH;
    int b = wg - t * BATCH;

    const int is64 = g_is64;
    long long lo, hi;
    if (is64) {
        const long long* off = (const long long*)offp + (size_t)t * BATCH;
        lo = (b == 0) ? 0 : off[b];
        hi = (b == BATCH - 1) ? (long long)NTPER : off[b + 1];
    } else {
        const int* off = (const int*)offp + (size_t)t * BATCH;
        lo = (b == 0) ? 0 : (long long)off[b];
        hi = (b == BATCH - 1) ? (long long)NTPER : (long long)off[b + 1];
    }

    const float* tab = tables + (size_t)t * EROWS * DEMB;
    float4 acc;
    if (is64) acc = pool_rows((const long long*)idxp + (size_t)t * NTPER, tab, lo, hi, lane);
    else      acc = pool_rows((const int*)idxp + (size_t)t * NTPER, tab, lo, hi, lane);

    const int col = (t + 1) * DEMB + lane * 4;
    *(float4*)(comb + (size_t)b * FIN + col) = acc;
    size_t o = (size_t)b * (2 * FIN) + col;
    split_store2(act2, o,     FIN, acc.x, acc.y);
    split_store2(act2, o + 2, FIN, acc.z, acc.w);
}

// ==================== weight conversion: fp32 -> fp16 (plain) ==============
__global__ void convB_kernel(const float* __restrict__ in, __half* __restrict__ out,
                             int total) {
    for (int i = blockIdx.x * blockDim.x + threadIdx.x; i < total;
         i += gridDim.x * blockDim.x)
        out[i] = __float2half_rn(in[i]);
}

// ==================== mma.sync fp16 GEMM: C = A2[M,2K] * B[N,K]^T ==========
// A is [h|l] split (K'=2K); B is single fp16 [N,K], read twice (kb mod NKBb).
// CTA tile 128x128, BK=64 elems (128B rows), 3-stage cp.async, 2 CTA/SM.
// 256 threads = 8 warps 4(m) x 2(n); warp tile 32x64.
// EPI: 1 = relu(acc+bias) -> fp32 Cf
//      2 = DCN: xlin = h+l from old C3; v = comb*(acc+bias)+xlin -> split C3
//      3 = split C3 only
//      4 = relu(acc+bias) -> split C3 only
__device__ __forceinline__ void load_stage(uint32_t base, int st, int kb, int nkbb,
                                           const char* Ab, const char* Bb,
                                           size_t rstrideA, size_t rstrideB,
                                           int row_r, int c16) {
    uint32_t sA = base + (uint32_t)st * 32768u;
    uint32_t sB = sA + 16384u;
    int kbB = (kb >= nkbb) ? kb - nkbb : kb;
    size_t koffA = (size_t)kb  * 128 + c16;
    size_t koffB = (size_t)kbB * 128 + c16;
#pragma unroll
    for (int j = 0; j < 4; j++) {
        int row = j * 32 + row_r;
        uint32_t so = SWZ((uint32_t)(row * 128 + c16));
        cp16(sA + so, Ab + (size_t)row * rstrideA + koffA);
        cp16(sB + so, Bb + (size_t)row * rstrideB + koffB);
    }
}

template<int EPI>
__global__ void __launch_bounds__(256, 2)
tc_gemm(const __half* __restrict__ A, const __half* __restrict__ B,
        const float* __restrict__ bias,
        float* __restrict__ Cf, int ldc,
        __half* __restrict__ C3, int Nout, int K3,   // K3 = 2*K (A's split width)
        const float* __restrict__ comb) {
    extern __shared__ char dsm[];
    const uint32_t base = (smem_u32(dsm) + 1023u) & ~1023u;

    const int tid  = threadIdx.x;
    const int wid  = tid >> 5, lane = tid & 31;
    const int wm   = wid & 3;
    const int wn   = wid >> 2;
    const int m0   = blockIdx.y * 128, n0 = blockIdx.x * 128;
    const int row_r = tid >> 3, c16 = (tid & 7) * 16;

    const int NKB  = K3 >> 6;
    const int NKBb = NKB >> 1;
    const char* Ab = (const char*)A + (size_t)m0 * K3 * 2;
    const char* Bb = (const char*)B + (size_t)n0 * (K3 / 2) * 2;
    const size_t rstrideA = (size_t)K3 * 2;
    const size_t rstrideB = (size_t)(K3 / 2) * 2;

    const int ar = lane & 15;
    const int ac = (lane >> 4) * 16;
    const int br = lane & 7;
    const int bn = ((lane >> 4) & 1) * 8;
    const int bc = ((lane >> 3) & 1) * 16;

    float acc[2][8][4];
#pragma unroll
    for (int i = 0; i < 2; i++)
#pragma unroll
        for (int j = 0; j < 8; j++)
#pragma unroll
            for (int e = 0; e < 4; e++) acc[i][j][e] = 0.f;

    for (int s = 0; s < STAGES - 1 && s < NKB; s++) {
        load_stage(base, s, s, NKBb, Ab, Bb, rstrideA, rstrideB, row_r, c16);
        cp_commit();
    }

    for (int kb = 0; kb < NKB; kb++) {
        const int st = kb % STAGES;
        cp_wait<STAGES - 2>();
        __syncthreads();

        const uint32_t sA = base + (uint32_t)st * 32768u;
        const uint32_t sB = sA + 16384u;
#pragma unroll
        for (int ks = 0; ks < 4; ks++) {
            const int kbyte = ks * 32;
            uint32_t a[2][4];
#pragma unroll
            for (int fm = 0; fm < 2; fm++) {
                uint32_t ad = sA + SWZ((uint32_t)((wm * 32 + fm * 16 + ar) * 128 + kbyte + ac));
                ldm_x4(a[fm][0], a[fm][1], a[fm][2], a[fm][3], ad);
            }
#pragma unroll
            for (int g = 0; g < 4; g++) {
                uint32_t b0, b1, b2, b3;
                uint32_t bd = sB + SWZ((uint32_t)((wn * 64 + g * 16 + bn + br) * 128 + kbyte + bc));
                ldm_x4(b0, b1, b2, b3, bd);
#pragma unroll
                for (int fm = 0; fm < 2; fm++) {
                    mma16816(acc[fm][2 * g],     a[fm], b0, b1);
                    mma16816(acc[fm][2 * g + 1], a[fm], b2, b3);
                }
            }
        }
        // slot refilled below was consumed last iteration; fenced by the
        // post-wait __syncthreads() above.
        const int nk = kb + STAGES - 1;
        if (nk < NKB)
            load_stage(base, nk % STAGES, nk, NKBb, Ab, Bb, rstrideA, rstrideB, row_r, c16);
        cp_commit();
    }

    // ---------------- epilogue (register accumulators) ----------------
    const int er = lane >> 2;
    const int ec = (lane & 3) * 2;
#pragma unroll
    for (int fm = 0; fm < 2; fm++) {
#pragma unroll
        for (int fn = 0; fn < 8; fn++) {
            const int ng = n0 + wn * 64 + fn * 8 + ec;
#pragma unroll
            for (int rr = 0; rr < 2; rr++) {
                const int m = m0 + wm * 32 + fm * 16 + er + rr * 8;
                float v0 = acc[fm][fn][rr * 2 + 0];
                float v1 = acc[fm][fn][rr * 2 + 1];
                if (EPI == 1 || EPI == 4) {
                    v0 += bias[ng];     v0 = v0 > 0.f ? v0 : 0.f;
                    v1 += bias[ng + 1]; v1 = v1 > 0.f ? v1 : 0.f;
                }
                if (EPI == 2) {
                    size_t o3 = (size_t)m * (2 * Nout) + ng;
                    __half2 oh = *(const __half2*)(C3 + o3);
                    __half2 ol = *(const __half2*)(C3 + o3 + Nout);
                    float x0 = __half2float(oh.x) + __half2float(ol.x);
                    float x1 = __half2float(oh.y) + __half2float(ol.y);
                    float2 cb = *(const float2*)(comb + (size_t)m * ldc + ng);
                    v0 = cb.x * (v0 + bias[ng])     + x0;
                    v1 = cb.y * (v1 + bias[ng + 1]) + x1;
                }
                if (EPI == 1)
                    *(float2*)(Cf + (size_t)m * ldc + ng) = make_float2(v0, v1);
                if (EPI >= 2)
                    split_store2(C3, (size_t)m * (2 * Nout) + ng, Nout, v0, v1);
            }
        }
    }
}

// ==================== fp32 SGEMM (small bottom-MLP layers) =================
// EPI: 1 = relu -> fp32 C.   5 = relu -> fp32 C AND split C3.
template<int EPI>
__global__ void __launch_bounds__(256, 2)
sgemm_nt(const float* __restrict__ A, int lda,
         const float* __restrict__ Bm, int ldb,
         const float* __restrict__ bias,
         float* __restrict__ C, int ldc, int K,
         __half* __restrict__ C3, int Nout) {
    __shared__ __align__(16) float As[8][128];
    __shared__ __align__(16) float Bs[8][128];
    const int tid = threadIdx.x;
    const int m0 = blockIdx.y * 128, n0 = blockIdx.x * 128;
    const int lr = tid >> 1, lc = (tid & 1) * 4;
    const float* Ag = A + (size_t)(m0 + lr) * lda + lc;
    const float* Bg = Bm + (size_t)(n0 + lr) * ldb + lc;
    const int ty = tid >> 4, tx = tid & 15;

    float acc[8][8];
#pragma unroll
    for (int i = 0; i < 8; i++)
#pragma unroll
        for (int j = 0; j < 8; j++) acc[i][j] = 0.f;

    for (int k0 = 0; k0 < K; k0 += 8) {
#pragma unroll
        for (int j = 0; j < 4; j++) {
            int kk = k0 + lc + j;
            As[lc + j][lr] = (kk < K) ? Ag[k0 + j] : 0.f;
            Bs[lc + j][lr] = (kk < K) ? Bg[k0 + j] : 0.f;
        }
        __syncthreads();
#pragma unroll
        for (int k = 0; k < 8; k++) {
            float4 a0 = *(const float4*)&As[k][ty * 4];
            float4 a1 = *(const float4*)&As[k][64 + ty * 4];
            float4 b0 = *(const float4*)&Bs[k][tx * 4];
            float4 b1 = *(const float4*)&Bs[k][64 + tx * 4];
            float af[8] = {a0.x, a0.y, a0.z, a0.w, a1.x, a1.y, a1.z, a1.w};
            float bf[8] = {b0.x, b0.y, b0.z, b0.w, b1.x, b1.y, b1.z, b1.w};
#pragma unroll
            for (int i = 0; i < 8; i++)
#pragma unroll
                for (int j = 0; j < 8; j++) acc[i][j] += af[i] * bf[j];
        }
        __syncthreads();
    }
#pragma unroll
    for (int i = 0; i < 8; i++) {
        int mg = m0 + ((i < 4) ? (ty * 4 + i) : (64 + ty * 4 + (i - 4)));
        size_t rowoff = (size_t)mg * ldc;
#pragma unroll
        for (int j = 0; j < 8; j++) {
            int ng = n0 + ((j < 4) ? (tx * 4 + j) : (64 + tx * 4 + (j - 4)));
            float v = acc[i][j] + bias[ng];
            v = v > 0.f ? v : 0.f;
            C[rowoff + ng] = v;
            if (EPI == 5) {
                __half h = __float2half_rn(v);
                __half l = __float2half_rn(v - __half2float(h));
                size_t o = (size_t)mg * (2 * Nout) + ng;
                C3[o] = h; C3[o + Nout] = l;
            }
        }
    }
}

// ==================== final layer ====================
__global__ void final_kernel(const float* __restrict__ z, const float* __restrict__ w,
                             const float* __restrict__ b3, float* __restrict__ out) {
    int row = blockIdx.x;
    float s = 0.f;
    for (int j = threadIdx.x; j < 512; j += 128)
        s += z[(size_t)row * 512 + j] * w[j];
#pragma unroll
    for (int o = 16; o > 0; o >>= 1) s += __shfl_down_sync(0xffffffffu, s, o);
    __shared__ float sm[4];
    if ((threadIdx.x & 31) == 0) sm[threadIdx.x >> 5] = s;
    __syncthreads();
    if (threadIdx.x == 0) out[row] = sm[0] + sm[1] + sm[2] + sm[3] + b3[0];
}

// ==================== launch ====================
extern "C" void kernel_launch(void* const* d_in, const int* in_sizes, int n_in,
                              void* d_out, int out_size) {
    const float* dense   = (const float*)d_in[0];
    const void*  indices = d_in[1];
    const void*  offsets = d_in[2];
    const float* emb     = (const float*)d_in[3];
    const float* bW0 = (const float*)d_in[4];  const float* bb0 = (const float*)d_in[5];
    const float* bW1 = (const float*)d_in[6];  const float* bb1 = (const float*)d_in[7];
    const float* bW2 = (const float*)d_in[8];  const float* bb2 = (const float*)d_in[9];
    const float* dcnW = (const float*)d_in[10];
    const float* dcnV = (const float*)d_in[11];
    const float* dcnb = (const float*)d_in[12];
    const float* tW0 = (const float*)d_in[13]; const float* tb0 = (const float*)d_in[14];
    const float* tW1 = (const float*)d_in[15]; const float* tb1 = (const float*)d_in[16];
    const float* tW2 = (const float*)d_in[17]; const float* tb2 = (const float*)d_in[18];
    const float* tW3 = (const float*)d_in[19]; const float* tb3 = (const float*)d_in[20];

    float *bot0, *bot1, *comb, *z2;
    __half *act2, *act2b, *act2c, *xv2, *wb;
    cudaGetSymbolAddress((void**)&bot0, g_bot0);
    cudaGetSymbolAddress((void**)&bot1, g_bot1);
    cudaGetSymbolAddress((void**)&comb, g_comb);
    cudaGetSymbolAddress((void**)&z2,   g_z2);
    cudaGetSymbolAddress((void**)&act2,  g_act2);
    cudaGetSymbolAddress((void**)&act2b, g_act2b);
    cudaGetSymbolAddress((void**)&act2c, g_act2c);
    cudaGetSymbolAddress((void**)&xv2,   g_xv2);
    cudaGetSymbolAddress((void**)&wb,    g_wb);

    const int dynsmem = STAGES * 32768 + 1024;
    cudaFuncSetAttribute(tc_gemm<1>, cudaFuncAttributeMaxDynamicSharedMemorySize, dynsmem);
    cudaFuncSetAttribute(tc_gemm<2>, cudaFuncAttributeMaxDynamicSharedMemorySize, dynsmem);
    cudaFuncSetAttribute(tc_gemm<3>, cudaFuncAttributeMaxDynamicSharedMemorySize, dynsmem);
    cudaFuncSetAttribute(tc_gemm<4>, cudaFuncAttributeMaxDynamicSharedMemorySize, dynsmem);

    // --- bottom MLP: 13 -> 512 -> 256 -> 128 (relu); layer 3 writes comb + act2 slot 0
    sgemm_nt<1><<<dim3(4, 32), 256>>>(dense, 13,  bW0, 13,  bb0, bot0, 512, 13,  nullptr, 0);
    sgemm_nt<1><<<dim3(2, 32), 256>>>(bot0, 512,  bW1, 512, bb1, bot1, 256, 512, nullptr, 0);
    sgemm_nt<5><<<dim3(1, 32), 256>>>(bot1, 256,  bW2, 256, bb2, comb, FIN, 256, act2, FIN);

    // --- embedding-bag pooling into comb + act2 slots 1..26
    detect_kernel<<<1, 256>>>((const unsigned*)offsets, in_sizes[2]);
    pool_kernel<<<(NTAB * BATCH) / 8, 256>>>(indices, offsets, emb, comb, act2);

    // --- low-rank DCN (fp16 2-term split, K' = 2K); x_l lives in act2
    for (int l = 0; l < 3; l++) {
        convB_kernel<<<2048, 256>>>(dcnV + (size_t)l * LOWR * FIN, wb, LOWR * FIN);
        tc_gemm<3><<<dim3(LOWR / 128, 32), 256, dynsmem>>>(
            act2, wb, nullptr, nullptr, 0, xv2, LOWR, 2 * FIN, nullptr);

        convB_kernel<<<2048, 256>>>(dcnW + (size_t)l * FIN * LOWR, wb, FIN * LOWR);
        tc_gemm<2><<<dim3(FIN / 128, 32), 256, dynsmem>>>(
            xv2, wb, dcnb + (size_t)l * FIN, nullptr, FIN, act2, FIN, 2 * LOWR, comb);
    }

    // --- top MLP: 3456 -> 1024 -> 1024 -> 512 (relu) -> 1
    convB_kernel<<<2048, 256>>>(tW0, wb, 1024 * FIN);
    tc_gemm<4><<<dim3(8, 32), 256, dynsmem>>>(
        act2, wb, tb0, nullptr, 0, act2b, 1024, 2 * FIN, nullptr);

    convB_kernel<<<2048, 256>>>(tW1, wb, 1024 * 1024);
    tc_gemm<4><<<dim3(8, 32), 256, dynsmem>>>(
        act2b, wb, tb1, nullptr, 0, act2c, 1024, 2 * 1024, nullptr);

    convB_kernel<<<2048, 256>>>(tW2, wb, 512 * 1024);
    tc_gemm<1><<<dim3(4, 32), 256, dynsmem>>>(
        act2c, wb, tb2, z2, 512, nullptr, 0, 2 * 1024, nullptr);

    final_kernel<<<BATCH, 128>>>(z2, tW3, tb3, (float*)d_out);
}

// round 10
// speedup vs baseline: 5.8654x; 1.4158x over previous
#include <cuda_runtime.h>
#include <cuda_fp16.h>
#include <cstdint>
#include <cstddef>

// ---------------- problem constants ----------------
#define BATCH   4096
#define NTAB    26
#define DEMB    128
#define NTPER   81920
#define EROWS   100000
#define FIN     3456
#define LOWR    512
#define STAGES  3

// ---------------- scratch (device globals; no runtime alloc) ----------------
__device__ float  g_bot0[BATCH * 512];
__device__ float  g_bot1[BATCH * 256];
__device__ float  g_comb[BATCH * FIN];     // combined features (fp32, immutable)
__device__ float  g_xl  [BATCH * FIN];     // DCN running state (fp32 master)
__device__ float  g_z2  [BATCH * 512];
__device__ int    g_is64;
__device__ __half g_actA[BATCH * FIN];     // fp16 copy of current DCN input
__device__ __half g_z0h [BATCH * 1024];
__device__ __half g_z1h [BATCH * 1024];
__device__ __half g_xvh [BATCH * LOWR];
__device__ __half g_wb  [1024 * FIN];      // fp16 weight scratch (max tW0)

// ==================== PTX helpers ====================
__device__ __forceinline__ uint32_t smem_u32(const void* p) {
    uint32_t a;
    asm("{ .reg .u64 t; cvta.to.shared.u64 t, %1; cvt.u32.u64 %0, t; }" : "=r"(a) : "l"(p));
    return a;
}
#define SWZ(x) ((x) ^ (((x) >> 3) & 0x70))

__device__ __forceinline__ void cp16(uint32_t dst, const void* src) {
    asm volatile("cp.async.cg.shared.global [%0], [%1], 16;" :: "r"(dst), "l"(src) : "memory");
}
__device__ __forceinline__ void cp_commit() { asm volatile("cp.async.commit_group;" ::: "memory"); }
template<int N> __device__ __forceinline__ void cp_wait() {
    asm volatile("cp.async.wait_group %0;" :: "n"(N) : "memory");
}
__device__ __forceinline__ void ldm_x4(uint32_t& r0, uint32_t& r1, uint32_t& r2, uint32_t& r3,
                                       uint32_t addr) {
    asm volatile("ldmatrix.sync.aligned.m8n8.x4.shared.b16 {%0,%1,%2,%3}, [%4];"
                 : "=r"(r0), "=r"(r1), "=r"(r2), "=r"(r3) : "r"(addr));
}
__device__ __forceinline__ void mma16816(float* c, const uint32_t* a, uint32_t b0, uint32_t b1) {
    asm volatile(
        "mma.sync.aligned.m16n8k16.row.col.f32.f16.f16.f32 "
        "{%0,%1,%2,%3}, {%4,%5,%6,%7}, {%8,%9}, {%0,%1,%2,%3};"
        : "+f"(c[0]), "+f"(c[1]), "+f"(c[2]), "+f"(c[3])
        : "r"(a[0]), "r"(a[1]), "r"(a[2]), "r"(a[3]), "r"(b0), "r"(b1));
}

__device__ __forceinline__ void half_store2(__half* __restrict__ p, size_t o,
                                            float v0, float v1) {
    __half2 hh; hh.x = __float2half_rn(v0); hh.y = __float2half_rn(v1);
    *(__half2*)(p + o) = hh;
}

// ==================== dtype detection (int64 vs int32) ====================
__global__ void detect_kernel(const unsigned* __restrict__ words, int n_elems) {
    __shared__ unsigned red;
    if (threadIdx.x == 0) red = 0u;
    __syncthreads();
    int n = n_elems < 8192 ? n_elems : 8192;
    unsigned acc = 0u;
    for (int i = 1 + 2 * (int)threadIdx.x; i < n; i += 2 * (int)blockDim.x) acc |= words[i];
    if (acc) atomicOr(&red, 1u);
    __syncthreads();
    if (threadIdx.x == 0) g_is64 = (red == 0u) ? 1 : 0;
}

// ==================== embedding-bag pooling: one warp per (table, bag) ======
template<typename IT>
__device__ __forceinline__ float4 pool_rows(const IT* __restrict__ idx,
                                            const float* __restrict__ tab,
                                            long long lo, long long hi, int lane) {
    float4 acc = make_float4(0.f, 0.f, 0.f, 0.f);
    long long i = lo;
    for (; i + 4 <= hi; i += 4) {
        size_t r0 = (size_t)idx[i],     r1 = (size_t)idx[i + 1];
        size_t r2 = (size_t)idx[i + 2], r3 = (size_t)idx[i + 3];
        float4 v0 = *(const float4*)(tab + r0 * DEMB + lane * 4);
        float4 v1 = *(const float4*)(tab + r1 * DEMB + lane * 4);
        float4 v2 = *(const float4*)(tab + r2 * DEMB + lane * 4);
        float4 v3 = *(const float4*)(tab + r3 * DEMB + lane * 4);
        acc.x += v0.x + v1.x + v2.x + v3.x;
        acc.y += v0.y + v1.y + v2.y + v3.y;
        acc.z += v0.z + v1.z + v2.z + v3.z;
        acc.w += v0.w + v1.w + v2.w + v3.w;
    }
    for (; i < hi; ++i) {
        float4 v = *(const float4*)(tab + (size_t)idx[i] * DEMB + lane * 4);
        acc.x += v.x; acc.y += v.y; acc.z += v.z; acc.w += v.w;
    }
    return acc;
}

__global__ void pool_kernel(const void* __restrict__ idxp,
                            const void* __restrict__ offp,
                            const float* __restrict__ tables,
                            float* __restrict__ comb,
                            __half* __restrict__ actA) {
    int wg   = (blockIdx.x * blockDim.x + threadIdx.x) >> 5;
    int lane = threadIdx.x & 31;
    if (wg >= NTAB * BATCH) return;
    int t = wg / BATCH;
    int b = wg - t * BATCH;

    const int is64 = g_is64;
    long long lo, hi;
    if (is64) {
        const long long* off = (const long long*)offp + (size_t)t * BATCH;
        lo = (b == 0) ? 0 : off[b];
        hi = (b == BATCH - 1) ? (long long)NTPER : off[b + 1];
    } else {
        const int* off = (const int*)offp + (size_t)t * BATCH;
        lo = (b == 0) ? 0 : (long long)off[b];
        hi = (b == BATCH - 1) ? (long long)NTPER : (long long)off[b + 1];
    }

    const float* tab = tables + (size_t)t * EROWS * DEMB;
    float4 acc;
    if (is64) acc = pool_rows((const long long*)idxp + (size_t)t * NTPER, tab, lo, hi, lane);
    else      acc = pool_rows((const int*)idxp + (size_t)t * NTPER, tab, lo, hi, lane);

    const int col = (t + 1) * DEMB + lane * 4;
    *(float4*)(comb + (size_t)b * FIN + col) = acc;
    size_t o = (size_t)b * FIN + col;
    half_store2(actA, o,     acc.x, acc.y);
    half_store2(actA, o + 2, acc.z, acc.w);
}

// ==================== weight conversion: fp32 -> fp16 ====================
__global__ void convB_kernel(const float* __restrict__ in, __half* __restrict__ out,
                             int total) {
    for (int i = blockIdx.x * blockDim.x + threadIdx.x; i < total;
         i += gridDim.x * blockDim.x)
        out[i] = __float2half_rn(in[i]);
}

// ==================== mma.sync fp16 GEMM: C = A[M,K] * B[N,K]^T ============
// CTA tile 128x128, BK=64 elems (128B rows), 3-stage cp.async, 2 CTA/SM.
// 256 threads = 8 warps 4(m) x 2(n); warp tile 32x64.
// EPI: 1 = relu(acc+bias) -> fp32 Cf
//      2 = DCN: v = comb*(acc+bias)+xlin -> fp32 Cf AND fp16 Ch
//      3 = fp16 Ch raw
//      4 = relu(acc+bias) -> fp16 Ch
__device__ __forceinline__ void load_stage(uint32_t base, int st, int kb,
                                           const char* Ab, const char* Bb,
                                           size_t rstride, int row_r, int c16) {
    uint32_t sA = base + (uint32_t)st * 32768u;
    uint32_t sB = sA + 16384u;
    size_t koff = (size_t)kb * 128 + c16;
#pragma unroll
    for (int j = 0; j < 4; j++) {
        int row = j * 32 + row_r;
        uint32_t so = SWZ((uint32_t)(row * 128 + c16));
        cp16(sA + so, Ab + (size_t)row * rstride + koff);
        cp16(sB + so, Bb + (size_t)row * rstride + koff);
    }
}

template<int EPI>
__global__ void __launch_bounds__(256, 2)
tc_gemm(const __half* __restrict__ A, const __half* __restrict__ B,
        const float* __restrict__ bias,
        float* __restrict__ Cf, int ldc,
        __half* __restrict__ Ch, int ldh, int K,
        const float* __restrict__ comb, const float* __restrict__ xlin) {
    extern __shared__ char dsm[];
    const uint32_t base = (smem_u32(dsm) + 1023u) & ~1023u;

    const int tid  = threadIdx.x;
    const int wid  = tid >> 5, lane = tid & 31;
    const int wm   = wid & 3;
    const int wn   = wid >> 2;
    const int m0   = blockIdx.y * 128, n0 = blockIdx.x * 128;
    const int row_r = tid >> 3, c16 = (tid & 7) * 16;

    const int NKB = K >> 6;
    const char* Ab = (const char*)A + (size_t)m0 * K * 2;
    const char* Bb = (const char*)B + (size_t)n0 * K * 2;
    const size_t rstride = (size_t)K * 2;

    const int ar = lane & 15;
    const int ac = (lane >> 4) * 16;
    const int br = lane & 7;
    const int bn = ((lane >> 4) & 1) * 8;
    const int bc = ((lane >> 3) & 1) * 16;

    float acc[2][8][4];
#pragma unroll
    for (int i = 0; i < 2; i++)
#pragma unroll
        for (int j = 0; j < 8; j++)
#pragma unroll
            for (int e = 0; e < 4; e++) acc[i][j][e] = 0.f;

    for (int s = 0; s < STAGES - 1 && s < NKB; s++) {
        load_stage(base, s, s, Ab, Bb, rstride, row_r, c16);
        cp_commit();
    }

    for (int kb = 0; kb < NKB; kb++) {
        const int st = kb % STAGES;
        cp_wait<STAGES - 2>();
        __syncthreads();

        const uint32_t sA = base + (uint32_t)st * 32768u;
        const uint32_t sB = sA + 16384u;
#pragma unroll
        for (int ks = 0; ks < 4; ks++) {
            const int kbyte = ks * 32;
            uint32_t a[2][4];
#pragma unroll
            for (int fm = 0; fm < 2; fm++) {
                uint32_t ad = sA + SWZ((uint32_t)((wm * 32 + fm * 16 + ar) * 128 + kbyte + ac));
                ldm_x4(a[fm][0], a[fm][1], a[fm][2], a[fm][3], ad);
            }
#pragma unroll
            for (int g = 0; g < 4; g++) {
                uint32_t b0, b1, b2, b3;
                uint32_t bd = sB + SWZ((uint32_t)((wn * 64 + g * 16 + bn + br) * 128 + kbyte + bc));
                ldm_x4(b0, b1, b2, b3, bd);
#pragma unroll
                for (int fm = 0; fm < 2; fm++) {
                    mma16816(acc[fm][2 * g],     a[fm], b0, b1);
                    mma16816(acc[fm][2 * g + 1], a[fm], b2, b3);
                }
            }
        }
        // slot refilled below was consumed last iteration; fenced by the
        // post-wait __syncthreads() above.
        const int nk = kb + STAGES - 1;
        if (nk < NKB)
            load_stage(base, nk % STAGES, nk, Ab, Bb, rstride, row_r, c16);
        cp_commit();
    }

    // ---------------- epilogue (register accumulators) ----------------
    const int er = lane >> 2;
    const int ec = (lane & 3) * 2;
#pragma unroll
    for (int fm = 0; fm < 2; fm++) {
#pragma unroll
        for (int fn = 0; fn < 8; fn++) {
            const int ng = n0 + wn * 64 + fn * 8 + ec;
#pragma unroll
            for (int rr = 0; rr < 2; rr++) {
                const int m = m0 + wm * 32 + fm * 16 + er + rr * 8;
                float v0 = acc[fm][fn][rr * 2 + 0];
                float v1 = acc[fm][fn][rr * 2 + 1];
                if (EPI == 1 || EPI == 4) {
                    v0 += bias[ng];     v0 = v0 > 0.f ? v0 : 0.f;
                    v1 += bias[ng + 1]; v1 = v1 > 0.f ? v1 : 0.f;
                }
                if (EPI == 2) {
                    size_t o = (size_t)m * ldc + ng;
                    float2 cb = *(const float2*)(comb + o);
                    float2 xb = *(const float2*)(xlin + o);
                    v0 = cb.x * (v0 + bias[ng])     + xb.x;
                    v1 = cb.y * (v1 + bias[ng + 1]) + xb.y;
                }
                if (EPI == 1 || EPI == 2)
                    *(float2*)(Cf + (size_t)m * ldc + ng) = make_float2(v0, v1);
                if (EPI >= 2)
                    half_store2(Ch, (size_t)m * ldh + ng, v0, v1);
            }
        }
    }
}

// ==================== fp32 SGEMM (small bottom-MLP layers) =================
// EPI: 1 = relu -> fp32 C.   5 = relu -> fp32 C AND fp16 Ch.
template<int EPI>
__global__ void __launch_bounds__(256, 2)
sgemm_nt(const float* __restrict__ A, int lda,
         const float* __restrict__ Bm, int ldb,
         const float* __restrict__ bias,
         float* __restrict__ C, int ldc, int K,
         __half* __restrict__ Ch) {
    __shared__ __align__(16) float As[8][128];
    __shared__ __align__(16) float Bs[8][128];
    const int tid = threadIdx.x;
    const int m0 = blockIdx.y * 128, n0 = blockIdx.x * 128;
    const int lr = tid >> 1, lc = (tid & 1) * 4;
    const float* Ag = A + (size_t)(m0 + lr) * lda + lc;
    const float* Bg = Bm + (size_t)(n0 + lr) * ldb + lc;
    const int ty = tid >> 4, tx = tid & 15;

    float acc[8][8];
#pragma unroll
    for (int i = 0; i < 8; i++)
#pragma unroll
        for (int j = 0; j < 8; j++) acc[i][j] = 0.f;

    for (int k0 = 0; k0 < K; k0 += 8) {
#pragma unroll
        for (int j = 0; j < 4; j++) {
            int kk = k0 + lc + j;
            As[lc + j][lr] = (kk < K) ? Ag[k0 + j] : 0.f;
            Bs[lc + j][lr] = (kk < K) ? Bg[k0 + j] : 0.f;
        }
        __syncthreads();
#pragma unroll
        for (int k = 0; k < 8; k++) {
            float4 a0 = *(const float4*)&As[k][ty * 4];
            float4 a1 = *(const float4*)&As[k][64 + ty * 4];
            float4 b0 = *(const float4*)&Bs[k][tx * 4];
            float4 b1 = *(const float4*)&Bs[k][64 + tx * 4];
            float af[8] = {a0.x, a0.y, a0.z, a0.w, a1.x, a1.y, a1.z, a1.w};
            float bf[8] = {b0.x, b0.y, b0.z, b0.w, b1.x, b1.y, b1.z, b1.w};
#pragma unroll
            for (int i = 0; i < 8; i++)
#pragma unroll
                for (int j = 0; j < 8; j++) acc[i][j] += af[i] * bf[j];
        }
        __syncthreads();
    }
#pragma unroll
    for (int i = 0; i < 8; i++) {
        int mg = m0 + ((i < 4) ? (ty * 4 + i) : (64 + ty * 4 + (i - 4)));
        size_t rowoff = (size_t)mg * ldc;
#pragma unroll
        for (int j = 0; j < 8; j++) {
            int ng = n0 + ((j < 4) ? (tx * 4 + j) : (64 + tx * 4 + (j - 4)));
            float v = acc[i][j] + bias[ng];
            v = v > 0.f ? v : 0.f;
            C[rowoff + ng] = v;
            if (EPI == 5)
                Ch[rowoff + ng] = __float2half_rn(v);
        }
    }
}

// ==================== final layer ====================
__global__ void final_kernel(const float* __restrict__ z, const float* __restrict__ w,
                             const float* __restrict__ b3, float* __restrict__ out) {
    int row = blockIdx.x;
    float s = 0.f;
    for (int j = threadIdx.x; j < 512; j += 128)
        s += z[(size_t)row * 512 + j] * w[j];
#pragma unroll
    for (int o = 16; o > 0; o >>= 1) s += __shfl_down_sync(0xffffffffu, s, o);
    __shared__ float sm[4];
    if ((threadIdx.x & 31) == 0) sm[threadIdx.x >> 5] = s;
    __syncthreads();
    if (threadIdx.x == 0) out[row] = sm[0] + sm[1] + sm[2] + sm[3] + b3[0];
}

// ==================== launch ====================
extern "C" void kernel_launch(void* const* d_in, const int* in_sizes, int n_in,
                              void* d_out, int out_size) {
    const float* dense   = (const float*)d_in[0];
    const void*  indices = d_in[1];
    const void*  offsets = d_in[2];
    const float* emb     = (const float*)d_in[3];
    const float* bW0 = (const float*)d_in[4];  const float* bb0 = (const float*)d_in[5];
    const float* bW1 = (const float*)d_in[6];  const float* bb1 = (const float*)d_in[7];
    const float* bW2 = (const float*)d_in[8];  const float* bb2 = (const float*)d_in[9];
    const float* dcnW = (const float*)d_in[10];
    const float* dcnV = (const float*)d_in[11];
    const float* dcnb = (const float*)d_in[12];
    const float* tW0 = (const float*)d_in[13]; const float* tb0 = (const float*)d_in[14];
    const float* tW1 = (const float*)d_in[15]; const float* tb1 = (const float*)d_in[16];
    const float* tW2 = (const float*)d_in[17]; const float* tb2 = (const float*)d_in[18];
    const float* tW3 = (const float*)d_in[19]; const float* tb3 = (const float*)d_in[20];

    float *bot0, *bot1, *comb, *xl, *z2;
    __half *actA, *z0h, *z1h, *xvh, *wb;
    cudaGetSymbolAddress((void**)&bot0, g_bot0);
    cudaGetSymbolAddress((void**)&bot1, g_bot1);
    cudaGetSymbolAddress((void**)&comb, g_comb);
    cudaGetSymbolAddress((void**)&xl,   g_xl);
    cudaGetSymbolAddress((void**)&z2,   g_z2);
    cudaGetSymbolAddress((void**)&actA, g_actA);
    cudaGetSymbolAddress((void**)&z0h,  g_z0h);
    cudaGetSymbolAddress((void**)&z1h,  g_z1h);
    cudaGetSymbolAddress((void**)&xvh,  g_xvh);
    cudaGetSymbolAddress((void**)&wb,   g_wb);

    const int dynsmem = STAGES * 32768 + 1024;
    cudaFuncSetAttribute(tc_gemm<1>, cudaFuncAttributeMaxDynamicSharedMemorySize, dynsmem);
    cudaFuncSetAttribute(tc_gemm<2>, cudaFuncAttributeMaxDynamicSharedMemorySize, dynsmem);
    cudaFuncSetAttribute(tc_gemm<3>, cudaFuncAttributeMaxDynamicSharedMemorySize, dynsmem);
    cudaFuncSetAttribute(tc_gemm<4>, cudaFuncAttributeMaxDynamicSharedMemorySize, dynsmem);

    // --- bottom MLP: 13 -> 512 -> 256 -> 128 (relu); layer 3 writes comb + actA slot 0
    sgemm_nt<1><<<dim3(4, 32), 256>>>(dense, 13,  bW0, 13,  bb0, bot0, 512, 13,  nullptr);
    sgemm_nt<1><<<dim3(2, 32), 256>>>(bot0, 512,  bW1, 512, bb1, bot1, 256, 512, nullptr);
    sgemm_nt<5><<<dim3(1, 32), 256>>>(bot1, 256,  bW2, 256, bb2, comb, FIN, 256, actA);

    // --- embedding-bag pooling into comb + actA slots 1..26
    detect_kernel<<<1, 256>>>((const unsigned*)offsets, in_sizes[2]);
    pool_kernel<<<(NTAB * BATCH) / 8, 256>>>(indices, offsets, emb, comb, actA);

    // --- low-rank DCN (plain fp16 GEMMs; x_l master in fp32, fp16 feed in actA)
    for (int l = 0; l < 3; l++) {
        const float* xlin = (l == 0) ? comb : xl;
        convB_kernel<<<2048, 256>>>(dcnV + (size_t)l * LOWR * FIN, wb, LOWR * FIN);
        tc_gemm<3><<<dim3(LOWR / 128, 32), 256, dynsmem>>>(
            actA, wb, nullptr, nullptr, 0, xvh, LOWR, FIN, nullptr, nullptr);

        convB_kernel<<<2048, 256>>>(dcnW + (size_t)l * FIN * LOWR, wb, FIN * LOWR);
        tc_gemm<2><<<dim3(FIN / 128, 32), 256, dynsmem>>>(
            xvh, wb, dcnb + (size_t)l * FIN, xl, FIN, actA, FIN, LOWR, comb, xlin);
    }

    // --- top MLP: 3456 -> 1024 -> 1024 -> 512 (relu) -> 1
    convB_kernel<<<2048, 256>>>(tW0, wb, 1024 * FIN);
    tc_gemm<4><<<dim3(8, 32), 256, dynsmem>>>(
        actA, wb, tb0, nullptr, 0, z0h, 1024, FIN, nullptr, nullptr);

    convB_kernel<<<2048, 256>>>(tW1, wb, 1024 * 1024);
    tc_gemm<4><<<dim3(8, 32), 256, dynsmem>>>(
        z0h, wb, tb1, nullptr, 0, z1h, 1024, 1024, nullptr, nullptr);

    convB_kernel<<<2048, 256>>>(tW2, wb, 512 * 1024);
    tc_gemm<1><<<dim3(4, 32), 256, dynsmem>>>(
        z1h, wb, tb2, z2, 512, nullptr, 0, 1024, nullptr, nullptr);

    final_kernel<<<BATCH, 128>>>(z2, tW3, tb3, (float*)d_out);
}

// round 11
// speedup vs baseline: 6.2947x; 1.0732x over previous
#include <cuda_runtime.h>
#include <cuda_fp16.h>
#include <cstdint>
#include <cstddef>

// ---------------- problem constants ----------------
#define BATCH   4096
#define NTAB    26
#define DEMB    128
#define NTPER   81920
#define EROWS   100000
#define FIN     3456
#define LOWR    512
#define STAGES  3

// ---------------- scratch (device globals; no runtime alloc) ----------------
__device__ float  g_bot0[BATCH * 512];
__device__ float  g_bot1[BATCH * 256];
__device__ float  g_comb[BATCH * FIN];     // combined features (fp32, immutable)
__device__ float  g_xl  [BATCH * FIN];     // DCN running state (fp32 master)
__device__ int    g_is64;
__device__ __half g_actA[BATCH * FIN];     // fp16 copy of current DCN input
__device__ __half g_z0h [BATCH * 1024];
__device__ __half g_z1h [BATCH * 1024];
__device__ __half g_xvh [BATCH * LOWR];
// dedicated fp16 weight buffers (converted once per call, no serialization)
__device__ __half g_wV [3 * LOWR * FIN];
__device__ __half g_wW [3 * FIN * LOWR];
__device__ __half g_wT0[1024 * FIN];
__device__ __half g_wT1[1024 * 1024];
__device__ __half g_wT2[512 * 1024];

// ==================== PTX helpers ====================
__device__ __forceinline__ uint32_t smem_u32(const void* p) {
    uint32_t a;
    asm("{ .reg .u64 t; cvta.to.shared.u64 t, %1; cvt.u32.u64 %0, t; }" : "=r"(a) : "l"(p));
    return a;
}
#define SWZ(x) ((x) ^ (((x) >> 3) & 0x70))

__device__ __forceinline__ void cp16(uint32_t dst, const void* src) {
    asm volatile("cp.async.cg.shared.global [%0], [%1], 16;" :: "r"(dst), "l"(src) : "memory");
}
__device__ __forceinline__ void cp_commit() { asm volatile("cp.async.commit_group;" ::: "memory"); }
template<int N> __device__ __forceinline__ void cp_wait() {
    asm volatile("cp.async.wait_group %0;" :: "n"(N) : "memory");
}
__device__ __forceinline__ void ldm_x4(uint32_t& r0, uint32_t& r1, uint32_t& r2, uint32_t& r3,
                                       uint32_t addr) {
    asm volatile("ldmatrix.sync.aligned.m8n8.x4.shared.b16 {%0,%1,%2,%3}, [%4];"
                 : "=r"(r0), "=r"(r1), "=r"(r2), "=r"(r3) : "r"(addr));
}
__device__ __forceinline__ void mma16816(float* c, const uint32_t* a, uint32_t b0, uint32_t b1) {
    asm volatile(
        "mma.sync.aligned.m16n8k16.row.col.f32.f16.f16.f32 "
        "{%0,%1,%2,%3}, {%4,%5,%6,%7}, {%8,%9}, {%0,%1,%2,%3};"
        : "+f"(c[0]), "+f"(c[1]), "+f"(c[2]), "+f"(c[3])
        : "r"(a[0]), "r"(a[1]), "r"(a[2]), "r"(a[3]), "r"(b0), "r"(b1));
}

__device__ __forceinline__ void half_store2(__half* __restrict__ p, size_t o,
                                            float v0, float v1) {
    __half2 hh; hh.x = __float2half_rn(v0); hh.y = __float2half_rn(v1);
    *(__half2*)(p + o) = hh;
}

// ==================== fused conversion + detect + out-init =================
struct ConvArgs {
    const float* src[5];
    __half*      dst[5];
    int          n[5];
    int          total;
    const unsigned* offwords;
    int          offn;
    float*       out;       // d_out, init to b3[0]
    const float* b3;
};

__global__ void convall_kernel(ConvArgs a) {
    if (blockIdx.x == 0) {   // int64-vs-int32 detection on offsets buffer
        __shared__ unsigned red;
        if (threadIdx.x == 0) red = 0u;
        __syncthreads();
        int n = a.offn < 8192 ? a.offn : 8192;
        unsigned acc = 0u;
        for (int i = 1 + 2 * (int)threadIdx.x; i < n; i += 2 * (int)blockDim.x)
            acc |= a.offwords[i];
        if (acc) atomicOr(&red, 1u);
        __syncthreads();
        if (threadIdx.x == 0) g_is64 = (red == 0u) ? 1 : 0;
    }
    if (blockIdx.x == 1) {   // init final output to bias b3
        float b = a.b3[0];
        for (int i = threadIdx.x; i < BATCH; i += blockDim.x) a.out[i] = b;
    }
    for (int gid = blockIdx.x * blockDim.x + threadIdx.x; gid < a.total;
         gid += gridDim.x * blockDim.x) {
        int i = gid;
#pragma unroll
        for (int s = 0; s < 5; s++) {
            if (i < a.n[s]) { a.dst[s][i] = __float2half_rn(a.src[s][i]); break; }
            i -= a.n[s];
        }
    }
}

// ==================== embedding-bag pooling: one warp per (table, bag) ======
template<typename IT>
__device__ __forceinline__ float4 pool_rows(const IT* __restrict__ idx,
                                            const float* __restrict__ tab,
                                            long long lo, long long hi, int lane) {
    float4 acc = make_float4(0.f, 0.f, 0.f, 0.f);
    long long i = lo;
    for (; i + 4 <= hi; i += 4) {
        size_t r0 = (size_t)idx[i],     r1 = (size_t)idx[i + 1];
        size_t r2 = (size_t)idx[i + 2], r3 = (size_t)idx[i + 3];
        float4 v0 = *(const float4*)(tab + r0 * DEMB + lane * 4);
        float4 v1 = *(const float4*)(tab + r1 * DEMB + lane * 4);
        float4 v2 = *(const float4*)(tab + r2 * DEMB + lane * 4);
        float4 v3 = *(const float4*)(tab + r3 * DEMB + lane * 4);
        acc.x += v0.x + v1.x + v2.x + v3.x;
        acc.y += v0.y + v1.y + v2.y + v3.y;
        acc.z += v0.z + v1.z + v2.z + v3.z;
        acc.w += v0.w + v1.w + v2.w + v3.w;
    }
    for (; i < hi; ++i) {
        float4 v = *(const float4*)(tab + (size_t)idx[i] * DEMB + lane * 4);
        acc.x += v.x; acc.y += v.y; acc.z += v.z; acc.w += v.w;
    }
    return acc;
}

__global__ void pool_kernel(const void* __restrict__ idxp,
                            const void* __restrict__ offp,
                            const float* __restrict__ tables,
                            float* __restrict__ comb,
                            __half* __restrict__ actA) {
    int wg   = (blockIdx.x * blockDim.x + threadIdx.x) >> 5;
    int lane = threadIdx.x & 31;
    if (wg >= NTAB * BATCH) return;
    int t = wg / BATCH;
    int b = wg - t * BATCH;

    const int is64 = g_is64;
    long long lo, hi;
    if (is64) {
        const long long* off = (const long long*)offp + (size_t)t * BATCH;
        lo = (b == 0) ? 0 : off[b];
        hi = (b == BATCH - 1) ? (long long)NTPER : off[b + 1];
    } else {
        const int* off = (const int*)offp + (size_t)t * BATCH;
        lo = (b == 0) ? 0 : (long long)off[b];
        hi = (b == BATCH - 1) ? (long long)NTPER : (long long)off[b + 1];
    }

    const float* tab = tables + (size_t)t * EROWS * DEMB;
    float4 acc;
    if (is64) acc = pool_rows((const long long*)idxp + (size_t)t * NTPER, tab, lo, hi, lane);
    else      acc = pool_rows((const int*)idxp + (size_t)t * NTPER, tab, lo, hi, lane);

    const int col = (t + 1) * DEMB + lane * 4;
    *(float4*)(comb + (size_t)b * FIN + col) = acc;
    size_t o = (size_t)b * FIN + col;
    half_store2(actA, o,     acc.x, acc.y);
    half_store2(actA, o + 2, acc.z, acc.w);
}

// ==================== mma.sync fp16 GEMM: C = A[M,K] * B[N,K]^T ============
// CTA tile 128x128, BK=64, 3-stage cp.async, 2 CTA/SM.
// 128 threads = 4 warps in 2(m) x 2(n); warp tile 64x64 (MMA:LDSM = 4).
// EPI: 2 = DCN: v = comb*(acc+bias)+xlin -> fp32 Cf AND fp16 Ch
//      3 = fp16 Ch raw
//      4 = relu(acc+bias) -> fp16 Ch
//      6 = relu(acc+bias), dot with w3 (aux), atomicAdd into Cf (pre-init b3)
__device__ __forceinline__ void load_stage(uint32_t base, int st, int kb,
                                           const char* Ab, const char* Bb,
                                           size_t rstride, int row_r, int c16) {
    uint32_t sA = base + (uint32_t)st * 32768u;
    uint32_t sB = sA + 16384u;
    size_t koff = (size_t)kb * 128 + c16;
#pragma unroll
    for (int j = 0; j < 8; j++) {
        int row = j * 16 + row_r;
        uint32_t so = SWZ((uint32_t)(row * 128 + c16));
        cp16(sA + so, Ab + (size_t)row * rstride + koff);
        cp16(sB + so, Bb + (size_t)row * rstride + koff);
    }
}

template<int EPI>
__global__ void __launch_bounds__(128, 2)
tc_gemm(const __half* __restrict__ A, const __half* __restrict__ B,
        const float* __restrict__ bias,
        float* __restrict__ Cf, int ldc,
        __half* __restrict__ Ch, int ldh, int K,
        const float* __restrict__ aux, const float* __restrict__ xlin) {
    extern __shared__ char dsm[];
    const uint32_t base = (smem_u32(dsm) + 1023u) & ~1023u;

    const int tid  = threadIdx.x;
    const int wid  = tid >> 5, lane = tid & 31;
    const int wm   = wid & 1;        // 2 m-warps * 64 rows
    const int wn   = wid >> 1;       // 2 n-warps * 64 cols
    const int m0   = blockIdx.y * 128, n0 = blockIdx.x * 128;
    const int row_r = tid >> 3, c16 = (tid & 7) * 16;

    const int NKB = K >> 6;
    const char* Ab = (const char*)A + (size_t)m0 * K * 2;
    const char* Bb = (const char*)B + (size_t)n0 * K * 2;
    const size_t rstride = (size_t)K * 2;

    const int ar = lane & 15;
    const int ac = (lane >> 4) * 16;
    const int br = lane & 7;
    const int bn = ((lane >> 4) & 1) * 8;
    const int bc = ((lane >> 3) & 1) * 16;

    float acc[4][8][4];
#pragma unroll
    for (int i = 0; i < 4; i++)
#pragma unroll
        for (int j = 0; j < 8; j++)
#pragma unroll
            for (int e = 0; e < 4; e++) acc[i][j][e] = 0.f;

    for (int s = 0; s < STAGES - 1 && s < NKB; s++) {
        load_stage(base, s, s, Ab, Bb, rstride, row_r, c16);
        cp_commit();
    }

    for (int kb = 0; kb < NKB; kb++) {
        const int st = kb % STAGES;
        cp_wait<STAGES - 2>();
        __syncthreads();

        const uint32_t sA = base + (uint32_t)st * 32768u;
        const uint32_t sB = sA + 16384u;
#pragma unroll
        for (int ks = 0; ks < 4; ks++) {
            const int kbyte = ks * 32;
            uint32_t a[4][4];
#pragma unroll
            for (int fm = 0; fm < 4; fm++) {
                uint32_t ad = sA + SWZ((uint32_t)((wm * 64 + fm * 16 + ar) * 128 + kbyte + ac));
                ldm_x4(a[fm][0], a[fm][1], a[fm][2], a[fm][3], ad);
            }
#pragma unroll
            for (int g = 0; g < 4; g++) {
                uint32_t b0, b1, b2, b3;
                uint32_t bd = sB + SWZ((uint32_t)((wn * 64 + g * 16 + bn + br) * 128 + kbyte + bc));
                ldm_x4(b0, b1, b2, b3, bd);
#pragma unroll
                for (int fm = 0; fm < 4; fm++) {
                    mma16816(acc[fm][2 * g],     a[fm], b0, b1);
                    mma16816(acc[fm][2 * g + 1], a[fm], b2, b3);
                }
            }
        }
        // slot refilled below was consumed last iteration; fenced by the
        // post-wait __syncthreads() above.
        const int nk = kb + STAGES - 1;
        if (nk < NKB)
            load_stage(base, nk % STAGES, nk, Ab, Bb, rstride, row_r, c16);
        cp_commit();
    }

    // ---------------- epilogue (register accumulators) ----------------
    const int er = lane >> 2;
    const int ec = (lane & 3) * 2;
    float fs[4][2];
    if (EPI == 6) {
#pragma unroll
        for (int i = 0; i < 4; i++) { fs[i][0] = 0.f; fs[i][1] = 0.f; }
    }
#pragma unroll
    for (int fm = 0; fm < 4; fm++) {
#pragma unroll
        for (int fn = 0; fn < 8; fn++) {
            const int ng = n0 + wn * 64 + fn * 8 + ec;
#pragma unroll
            for (int rr = 0; rr < 2; rr++) {
                const int m = m0 + wm * 64 + fm * 16 + er + rr * 8;
                float v0 = acc[fm][fn][rr * 2 + 0];
                float v1 = acc[fm][fn][rr * 2 + 1];
                if (EPI == 4 || EPI == 6) {
                    v0 += bias[ng];     v0 = v0 > 0.f ? v0 : 0.f;
                    v1 += bias[ng + 1]; v1 = v1 > 0.f ? v1 : 0.f;
                }
                if (EPI == 2) {
                    size_t o = (size_t)m * ldc + ng;
                    float2 cb = *(const float2*)(aux + o);
                    float2 xb = *(const float2*)(xlin + o);
                    v0 = cb.x * (v0 + bias[ng])     + xb.x;
                    v1 = cb.y * (v1 + bias[ng + 1]) + xb.y;
                    *(float2*)(Cf + o) = make_float2(v0, v1);
                }
                if (EPI == 6)
                    fs[fm][rr] += v0 * aux[ng] + v1 * aux[ng + 1];
                if (EPI == 2 || EPI == 3 || EPI == 4)
                    half_store2(Ch, (size_t)m * ldh + ng, v0, v1);
            }
        }
    }
    if (EPI == 6) {
#pragma unroll
        for (int fm = 0; fm < 4; fm++)
#pragma unroll
            for (int rr = 0; rr < 2; rr++) {
                float s = fs[fm][rr];
                s += __shfl_xor_sync(0xffffffffu, s, 1);
                s += __shfl_xor_sync(0xffffffffu, s, 2);
                if ((lane & 3) == 0) {
                    const int m = m0 + wm * 64 + fm * 16 + er + rr * 8;
                    atomicAdd(&Cf[m], s);
                }
            }
    }
}

// ==================== fp32 SGEMM (small bottom-MLP layers) =================
// EPI: 1 = relu -> fp32 C.   5 = relu -> fp32 C AND fp16 Ch.
template<int EPI>
__global__ void __launch_bounds__(256, 2)
sgemm_nt(const float* __restrict__ A, int lda,
         const float* __restrict__ Bm, int ldb,
         const float* __restrict__ bias,
         float* __restrict__ C, int ldc, int K,
         __half* __restrict__ Ch) {
    __shared__ __align__(16) float As[8][128];
    __shared__ __align__(16) float Bs[8][128];
    const int tid = threadIdx.x;
    const int m0 = blockIdx.y * 128, n0 = blockIdx.x * 128;
    const int lr = tid >> 1, lc = (tid & 1) * 4;
    const float* Ag = A + (size_t)(m0 + lr) * lda + lc;
    const float* Bg = Bm + (size_t)(n0 + lr) * ldb + lc;
    const int ty = tid >> 4, tx = tid & 15;

    float acc[8][8];
#pragma unroll
    for (int i = 0; i < 8; i++)
#pragma unroll
        for (int j = 0; j < 8; j++) acc[i][j] = 0.f;

    for (int k0 = 0; k0 < K; k0 += 8) {
#pragma unroll
        for (int j = 0; j < 4; j++) {
            int kk = k0 + lc + j;
            As[lc + j][lr] = (kk < K) ? Ag[k0 + j] : 0.f;
            Bs[lc + j][lr] = (kk < K) ? Bg[k0 + j] : 0.f;
        }
        __syncthreads();
#pragma unroll
        for (int k = 0; k < 8; k++) {
            float4 a0 = *(const float4*)&As[k][ty * 4];
            float4 a1 = *(const float4*)&As[k][64 + ty * 4];
            float4 b0 = *(const float4*)&Bs[k][tx * 4];
            float4 b1 = *(const float4*)&Bs[k][64 + tx * 4];
            float af[8] = {a0.x, a0.y, a0.z, a0.w, a1.x, a1.y, a1.z, a1.w};
            float bf[8] = {b0.x, b0.y, b0.z, b0.w, b1.x, b1.y, b1.z, b1.w};
#pragma unroll
            for (int i = 0; i < 8; i++)
#pragma unroll
                for (int j = 0; j < 8; j++) acc[i][j] += af[i] * bf[j];
        }
        __syncthreads();
    }
#pragma unroll
    for (int i = 0; i < 8; i++) {
        int mg = m0 + ((i < 4) ? (ty * 4 + i) : (64 + ty * 4 + (i - 4)));
        size_t rowoff = (size_t)mg * ldc;
#pragma unroll
        for (int j = 0; j < 8; j++) {
            int ng = n0 + ((j < 4) ? (tx * 4 + j) : (64 + tx * 4 + (j - 4)));
            float v = acc[i][j] + bias[ng];
            v = v > 0.f ? v : 0.f;
            C[rowoff + ng] = v;
            if (EPI == 5)
                Ch[rowoff + ng] = __float2half_rn(v);
        }
    }
}

// ==================== launch ====================
extern "C" void kernel_launch(void* const* d_in, const int* in_sizes, int n_in,
                              void* d_out, int out_size) {
    const float* dense   = (const float*)d_in[0];
    const void*  indices = d_in[1];
    const void*  offsets = d_in[2];
    const float* emb     = (const float*)d_in[3];
    const float* bW0 = (const float*)d_in[4];  const float* bb0 = (const float*)d_in[5];
    const float* bW1 = (const float*)d_in[6];  const float* bb1 = (const float*)d_in[7];
    const float* bW2 = (const float*)d_in[8];  const float* bb2 = (const float*)d_in[9];
    const float* dcnW = (const float*)d_in[10];
    const float* dcnV = (const float*)d_in[11];
    const float* dcnb = (const float*)d_in[12];
    const float* tW0 = (const float*)d_in[13]; const float* tb0 = (const float*)d_in[14];
    const float* tW1 = (const float*)d_in[15]; const float* tb1 = (const float*)d_in[16];
    const float* tW2 = (const float*)d_in[17]; const float* tb2 = (const float*)d_in[18];
    const float* tW3 = (const float*)d_in[19]; const float* tb3 = (const float*)d_in[20];

    float *bot0, *bot1, *comb, *xl;
    __half *actA, *z0h, *z1h, *xvh, *wV, *wW, *wT0, *wT1, *wT2;
    cudaGetSymbolAddress((void**)&bot0, g_bot0);
    cudaGetSymbolAddress((void**)&bot1, g_bot1);
    cudaGetSymbolAddress((void**)&comb, g_comb);
    cudaGetSymbolAddress((void**)&xl,   g_xl);
    cudaGetSymbolAddress((void**)&actA, g_actA);
    cudaGetSymbolAddress((void**)&z0h,  g_z0h);
    cudaGetSymbolAddress((void**)&z1h,  g_z1h);
    cudaGetSymbolAddress((void**)&xvh,  g_xvh);
    cudaGetSymbolAddress((void**)&wV,   g_wV);
    cudaGetSymbolAddress((void**)&wW,   g_wW);
    cudaGetSymbolAddress((void**)&wT0,  g_wT0);
    cudaGetSymbolAddress((void**)&wT1,  g_wT1);
    cudaGetSymbolAddress((void**)&wT2,  g_wT2);

    const int dynsmem = STAGES * 32768 + 1024;
    cudaFuncSetAttribute(tc_gemm<2>, cudaFuncAttributeMaxDynamicSharedMemorySize, dynsmem);
    cudaFuncSetAttribute(tc_gemm<3>, cudaFuncAttributeMaxDynamicSharedMemorySize, dynsmem);
    cudaFuncSetAttribute(tc_gemm<4>, cudaFuncAttributeMaxDynamicSharedMemorySize, dynsmem);
    cudaFuncSetAttribute(tc_gemm<6>, cudaFuncAttributeMaxDynamicSharedMemorySize, dynsmem);

    // --- fused weight conversion + dtype detect + out init
    ConvArgs ca;
    ca.src[0] = dcnV; ca.dst[0] = wV;  ca.n[0] = 3 * LOWR * FIN;
    ca.src[1] = dcnW; ca.dst[1] = wW;  ca.n[1] = 3 * FIN * LOWR;
    ca.src[2] = tW0;  ca.dst[2] = wT0; ca.n[2] = 1024 * FIN;
    ca.src[3] = tW1;  ca.dst[3] = wT1; ca.n[3] = 1024 * 1024;
    ca.src[4] = tW2;  ca.dst[4] = wT2; ca.n[4] = 512 * 1024;
    ca.total = ca.n[0] + ca.n[1] + ca.n[2] + ca.n[3] + ca.n[4];
    ca.offwords = (const unsigned*)offsets;
    ca.offn = in_sizes[2];
    ca.out = (float*)d_out;
    ca.b3 = tb3;
    convall_kernel<<<2048, 256>>>(ca);

    // --- bottom MLP: 13 -> 512 -> 256 -> 128 (relu); layer 3 writes comb + actA slot 0
    sgemm_nt<1><<<dim3(4, 32), 256>>>(dense, 13,  bW0, 13,  bb0, bot0, 512, 13,  nullptr);
    sgemm_nt<1><<<dim3(2, 32), 256>>>(bot0, 512,  bW1, 512, bb1, bot1, 256, 512, nullptr);
    sgemm_nt<5><<<dim3(1, 32), 256>>>(bot1, 256,  bW2, 256, bb2, comb, FIN, 256, actA);

    // --- embedding-bag pooling into comb + actA slots 1..26
    pool_kernel<<<(NTAB * BATCH) / 8, 256>>>(indices, offsets, emb, comb, actA);

    // --- low-rank DCN (fp16 GEMMs; x_l master in fp32, fp16 feed in actA)
    for (int l = 0; l < 3; l++) {
        const float* xlin = (l == 0) ? comb : xl;
        tc_gemm<3><<<dim3(LOWR / 128, 32), 128, dynsmem>>>(
            actA, wV + (size_t)l * LOWR * FIN, nullptr, nullptr, 0,
            xvh, LOWR, FIN, nullptr, nullptr);
        tc_gemm<2><<<dim3(FIN / 128, 32), 128, dynsmem>>>(
            xvh, wW + (size_t)l * FIN * LOWR, dcnb + (size_t)l * FIN, xl, FIN,
            actA, FIN, LOWR, comb, xlin);
    }

    // --- top MLP: 3456 -> 1024 -> 1024 -> 512 (relu) -> 1 (fused dot)
    tc_gemm<4><<<dim3(8, 32), 128, dynsmem>>>(
        actA, wT0, tb0, nullptr, 0, z0h, 1024, FIN, nullptr, nullptr);
    tc_gemm<4><<<dim3(8, 32), 128, dynsmem>>>(
        z0h, wT1, tb1, nullptr, 0, z1h, 1024, 1024, nullptr, nullptr);
    tc_gemm<6><<<dim3(4, 32), 128, dynsmem>>>(
        z1h, wT2, tb2, (float*)d_out, 0, nullptr, 0, 1024, tW3, nullptr);
}

// round 12
// speedup vs baseline: 7.4592x; 1.1850x over previous
#include <cuda_runtime.h>
#include <cuda_fp16.h>
#include <cstdint>
#include <cstddef>

// ---------------- problem constants ----------------
#define BATCH   4096
#define NTAB    26
#define DEMB    128
#define NTPER   81920
#define EROWS   100000
#define FIN     3456
#define LOWR    512
#define STAGES  3

// ---------------- scratch (device globals; no runtime alloc) ----------------
__device__ float  g_bot0[BATCH * 512];
__device__ float  g_comb[BATCH * FIN];     // combined features (fp32, immutable)
__device__ float  g_xl  [BATCH * FIN];     // DCN running state (fp32 master)
__device__ int    g_is64;
__device__ __half g_actA[BATCH * FIN];     // fp16 copy of current DCN input
__device__ __half g_z0h [BATCH * 1024];    // also reused as bot0h (disjoint in time)
__device__ __half g_z1h [BATCH * 1024];    // also reused as bot1h
__device__ __half g_xvh [BATCH * LOWR];
// dedicated fp16 weight buffers (converted once per call, no serialization)
__device__ __half g_wV [3 * LOWR * FIN];
__device__ __half g_wW [3 * FIN * LOWR];
__device__ __half g_wT0[1024 * FIN];
__device__ __half g_wT1[1024 * 1024];
__device__ __half g_wT2[512 * 1024];
__device__ __half g_wB1[256 * 512];
__device__ __half g_wB2[128 * 256];

// ==================== PTX helpers ====================
__device__ __forceinline__ uint32_t smem_u32(const void* p) {
    uint32_t a;
    asm("{ .reg .u64 t; cvta.to.shared.u64 t, %1; cvt.u32.u64 %0, t; }" : "=r"(a) : "l"(p));
    return a;
}
#define SWZ(x) ((x) ^ (((x) >> 3) & 0x70))

__device__ __forceinline__ void cp16(uint32_t dst, const void* src) {
    asm volatile("cp.async.cg.shared.global [%0], [%1], 16;" :: "r"(dst), "l"(src) : "memory");
}
__device__ __forceinline__ void cp_commit() { asm volatile("cp.async.commit_group;" ::: "memory"); }
template<int N> __device__ __forceinline__ void cp_wait() {
    asm volatile("cp.async.wait_group %0;" :: "n"(N) : "memory");
}
__device__ __forceinline__ void ldm_x4(uint32_t& r0, uint32_t& r1, uint32_t& r2, uint32_t& r3,
                                       uint32_t addr) {
    asm volatile("ldmatrix.sync.aligned.m8n8.x4.shared.b16 {%0,%1,%2,%3}, [%4];"
                 : "=r"(r0), "=r"(r1), "=r"(r2), "=r"(r3) : "r"(addr));
}
__device__ __forceinline__ void mma16816(float* c, const uint32_t* a, uint32_t b0, uint32_t b1) {
    asm volatile(
        "mma.sync.aligned.m16n8k16.row.col.f32.f16.f16.f32 "
        "{%0,%1,%2,%3}, {%4,%5,%6,%7}, {%8,%9}, {%0,%1,%2,%3};"
        : "+f"(c[0]), "+f"(c[1]), "+f"(c[2]), "+f"(c[3])
        : "r"(a[0]), "r"(a[1]), "r"(a[2]), "r"(a[3]), "r"(b0), "r"(b1));
}

__device__ __forceinline__ void half_store2(__half* __restrict__ p, size_t o,
                                            float v0, float v1) {
    __half2 hh; hh.x = __float2half_rn(v0); hh.y = __float2half_rn(v1);
    *(__half2*)(p + o) = hh;
}

// ==================== fused conversion + detect + out-init =================
struct ConvArgs {
    const float* src[7];
    __half*      dst[7];
    int          n[7];
    int          total;
    const unsigned* offwords;
    int          offn;
    float*       out;       // d_out, init to b3[0]
    const float* b3;
};

__global__ void convall_kernel(ConvArgs a) {
    if (blockIdx.x == 0) {   // int64-vs-int32 detection on offsets buffer
        __shared__ unsigned red;
        if (threadIdx.x == 0) red = 0u;
        __syncthreads();
        int n = a.offn < 8192 ? a.offn : 8192;
        unsigned acc = 0u;
        for (int i = 1 + 2 * (int)threadIdx.x; i < n; i += 2 * (int)blockDim.x)
            acc |= a.offwords[i];
        if (acc) atomicOr(&red, 1u);
        __syncthreads();
        if (threadIdx.x == 0) g_is64 = (red == 0u) ? 1 : 0;
    }
    if (blockIdx.x == 1) {   // init final output to bias b3
        float b = a.b3[0];
        for (int i = threadIdx.x; i < BATCH; i += blockDim.x) a.out[i] = b;
    }
    for (int gid = blockIdx.x * blockDim.x + threadIdx.x; gid < a.total;
         gid += gridDim.x * blockDim.x) {
        int i = gid;
#pragma unroll
        for (int s = 0; s < 7; s++) {
            if (i < a.n[s]) { a.dst[s][i] = __float2half_rn(a.src[s][i]); break; }
            i -= a.n[s];
        }
    }
}

// ==================== embedding-bag pooling: one warp per (table, bag) ======
template<typename IT>
__device__ __forceinline__ float4 pool_rows(const IT* __restrict__ idx,
                                            const float* __restrict__ tab,
                                            long long lo, long long hi, int lane) {
    float4 acc = make_float4(0.f, 0.f, 0.f, 0.f);
    long long i = lo;
    for (; i + 4 <= hi; i += 4) {
        size_t r0 = (size_t)idx[i],     r1 = (size_t)idx[i + 1];
        size_t r2 = (size_t)idx[i + 2], r3 = (size_t)idx[i + 3];
        float4 v0 = *(const float4*)(tab + r0 * DEMB + lane * 4);
        float4 v1 = *(const float4*)(tab + r1 * DEMB + lane * 4);
        float4 v2 = *(const float4*)(tab + r2 * DEMB + lane * 4);
        float4 v3 = *(const float4*)(tab + r3 * DEMB + lane * 4);
        acc.x += v0.x + v1.x + v2.x + v3.x;
        acc.y += v0.y + v1.y + v2.y + v3.y;
        acc.z += v0.z + v1.z + v2.z + v3.z;
        acc.w += v0.w + v1.w + v2.w + v3.w;
    }
    for (; i < hi; ++i) {
        float4 v = *(const float4*)(tab + (size_t)idx[i] * DEMB + lane * 4);
        acc.x += v.x; acc.y += v.y; acc.z += v.z; acc.w += v.w;
    }
    return acc;
}

__global__ void pool_kernel(const void* __restrict__ idxp,
                            const void* __restrict__ offp,
                            const float* __restrict__ tables,
                            float* __restrict__ comb,
                            __half* __restrict__ actA) {
    int wg   = (blockIdx.x * blockDim.x + threadIdx.x) >> 5;
    int lane = threadIdx.x & 31;
    if (wg >= NTAB * BATCH) return;
    int t = wg / BATCH;
    int b = wg - t * BATCH;

    const int is64 = g_is64;
    long long lo, hi;
    if (is64) {
        const long long* off = (const long long*)offp + (size_t)t * BATCH;
        lo = (b == 0) ? 0 : off[b];
        hi = (b == BATCH - 1) ? (long long)NTPER : off[b + 1];
    } else {
        const int* off = (const int*)offp + (size_t)t * BATCH;
        lo = (b == 0) ? 0 : (long long)off[b];
        hi = (b == BATCH - 1) ? (long long)NTPER : (long long)off[b + 1];
    }

    const float* tab = tables + (size_t)t * EROWS * DEMB;
    float4 acc;
    if (is64) acc = pool_rows((const long long*)idxp + (size_t)t * NTPER, tab, lo, hi, lane);
    else      acc = pool_rows((const int*)idxp + (size_t)t * NTPER, tab, lo, hi, lane);

    const int col = (t + 1) * DEMB + lane * 4;
    *(float4*)(comb + (size_t)b * FIN + col) = acc;
    size_t o = (size_t)b * FIN + col;
    half_store2(actA, o,     acc.x, acc.y);
    half_store2(actA, o + 2, acc.z, acc.w);
}

// ==================== mma.sync fp16 GEMM: C = A[M,K] * B[N,K]^T ============
// CTA tile 128x128, BK=64, 3-stage cp.async, 2 CTA/SM.
// 128 threads = 4 warps in 2(m) x 2(n); warp tile 64x64 (MMA:LDSM = 4).
// EPI: 2 = DCN: v = aux*(acc+bias)+xlin -> fp32 Cf AND fp16 Ch
//      3 = fp16 Ch raw
//      4 = relu(acc+bias) -> fp16 Ch
//      6 = relu(acc+bias), dot with w3 (aux), atomicAdd into Cf (pre-init b3)
//      7 = relu(acc+bias) -> fp32 Cf AND fp16 Ch
__device__ __forceinline__ void load_stage(uint32_t base, int st, int kb,
                                           const char* Ab, const char* Bb,
                                           size_t rstride, int row_r, int c16) {
    uint32_t sA = base + (uint32_t)st * 32768u;
    uint32_t sB = sA + 16384u;
    size_t koff = (size_t)kb * 128 + c16;
#pragma unroll
    for (int j = 0; j < 8; j++) {
        int row = j * 16 + row_r;
        uint32_t so = SWZ((uint32_t)(row * 128 + c16));
        cp16(sA + so, Ab + (size_t)row * rstride + koff);
        cp16(sB + so, Bb + (size_t)row * rstride + koff);
    }
}

template<int EPI>
__global__ void __launch_bounds__(128, 2)
tc_gemm(const __half* __restrict__ A, const __half* __restrict__ B,
        const float* __restrict__ bias,
        float* __restrict__ Cf, int ldc,
        __half* __restrict__ Ch, int ldh, int K,
        const float* __restrict__ aux, const float* __restrict__ xlin) {
    extern __shared__ char dsm[];
    const uint32_t base = (smem_u32(dsm) + 1023u) & ~1023u;

    const int tid  = threadIdx.x;
    const int wid  = tid >> 5, lane = tid & 31;
    const int wm   = wid & 1;        // 2 m-warps * 64 rows
    const int wn   = wid >> 1;       // 2 n-warps * 64 cols
    const int m0   = blockIdx.y * 128, n0 = blockIdx.x * 128;
    const int row_r = tid >> 3, c16 = (tid & 7) * 16;

    const int NKB = K >> 6;
    const char* Ab = (const char*)A + (size_t)m0 * K * 2;
    const char* Bb = (const char*)B + (size_t)n0 * K * 2;
    const size_t rstride = (size_t)K * 2;

    const int ar = lane & 15;
    const int ac = (lane >> 4) * 16;
    const int br = lane & 7;
    const int bn = ((lane >> 4) & 1) * 8;
    const int bc = ((lane >> 3) & 1) * 16;

    float acc[4][8][4];
#pragma unroll
    for (int i = 0; i < 4; i++)
#pragma unroll
        for (int j = 0; j < 8; j++)
#pragma unroll
            for (int e = 0; e < 4; e++) acc[i][j][e] = 0.f;

    for (int s = 0; s < STAGES - 1 && s < NKB; s++) {
        load_stage(base, s, s, Ab, Bb, rstride, row_r, c16);
        cp_commit();
    }

    for (int kb = 0; kb < NKB; kb++) {
        const int st = kb % STAGES;
        cp_wait<STAGES - 2>();
        __syncthreads();

        const uint32_t sA = base + (uint32_t)st * 32768u;
        const uint32_t sB = sA + 16384u;
#pragma unroll
        for (int ks = 0; ks < 4; ks++) {
            const int kbyte = ks * 32;
            uint32_t a[4][4];
#pragma unroll
            for (int fm = 0; fm < 4; fm++) {
                uint32_t ad = sA + SWZ((uint32_t)((wm * 64 + fm * 16 + ar) * 128 + kbyte + ac));
                ldm_x4(a[fm][0], a[fm][1], a[fm][2], a[fm][3], ad);
            }
#pragma unroll
            for (int g = 0; g < 4; g++) {
                uint32_t b0, b1, b2, b3;
                uint32_t bd = sB + SWZ((uint32_t)((wn * 64 + g * 16 + bn + br) * 128 + kbyte + bc));
                ldm_x4(b0, b1, b2, b3, bd);
#pragma unroll
                for (int fm = 0; fm < 4; fm++) {
                    mma16816(acc[fm][2 * g],     a[fm], b0, b1);
                    mma16816(acc[fm][2 * g + 1], a[fm], b2, b3);
                }
            }
        }
        // slot refilled below was consumed last iteration; fenced by the
        // post-wait __syncthreads() above.
        const int nk = kb + STAGES - 1;
        if (nk < NKB)
            load_stage(base, nk % STAGES, nk, Ab, Bb, rstride, row_r, c16);
        cp_commit();
    }

    // ---------------- epilogue (register accumulators) ----------------
    const int er = lane >> 2;
    const int ec = (lane & 3) * 2;
    float fs[4][2];
    if (EPI == 6) {
#pragma unroll
        for (int i = 0; i < 4; i++) { fs[i][0] = 0.f; fs[i][1] = 0.f; }
    }
#pragma unroll
    for (int fm = 0; fm < 4; fm++) {
#pragma unroll
        for (int fn = 0; fn < 8; fn++) {
            const int ng = n0 + wn * 64 + fn * 8 + ec;
#pragma unroll
            for (int rr = 0; rr < 2; rr++) {
                const int m = m0 + wm * 64 + fm * 16 + er + rr * 8;
                float v0 = acc[fm][fn][rr * 2 + 0];
                float v1 = acc[fm][fn][rr * 2 + 1];
                if (EPI == 4 || EPI == 6 || EPI == 7) {
                    v0 += bias[ng];     v0 = v0 > 0.f ? v0 : 0.f;
                    v1 += bias[ng + 1]; v1 = v1 > 0.f ? v1 : 0.f;
                }
                if (EPI == 2) {
                    size_t o = (size_t)m * ldc + ng;
                    float2 cb = *(const float2*)(aux + o);
                    float2 xb = *(const float2*)(xlin + o);
                    v0 = cb.x * (v0 + bias[ng])     + xb.x;
                    v1 = cb.y * (v1 + bias[ng + 1]) + xb.y;
                    *(float2*)(Cf + o) = make_float2(v0, v1);
                }
                if (EPI == 7)
                    *(float2*)(Cf + (size_t)m * ldc + ng) = make_float2(v0, v1);
                if (EPI == 6)
                    fs[fm][rr] += v0 * aux[ng] + v1 * aux[ng + 1];
                if (EPI == 2 || EPI == 3 || EPI == 4 || EPI == 7)
                    half_store2(Ch, (size_t)m * ldh + ng, v0, v1);
            }
        }
    }
    if (EPI == 6) {
#pragma unroll
        for (int fm = 0; fm < 4; fm++)
#pragma unroll
            for (int rr = 0; rr < 2; rr++) {
                float s = fs[fm][rr];
                s += __shfl_xor_sync(0xffffffffu, s, 1);
                s += __shfl_xor_sync(0xffffffffu, s, 2);
                if ((lane & 3) == 0) {
                    const int m = m0 + wm * 64 + fm * 16 + er + rr * 8;
                    atomicAdd(&Cf[m], s);
                }
            }
    }
}

// ==================== fp32 SGEMM (bottom layer 1 only, K=13) ===============
// EPI 5 = relu -> fp32 C AND fp16 Ch (same ld).
__global__ void __launch_bounds__(256, 2)
sgemm_l1(const float* __restrict__ A, int lda,
         const float* __restrict__ Bm, int ldb,
         const float* __restrict__ bias,
         float* __restrict__ C, int ldc, int K,
         __half* __restrict__ Ch) {
    __shared__ __align__(16) float As[8][128];
    __shared__ __align__(16) float Bs[8][128];
    const int tid = threadIdx.x;
    const int m0 = blockIdx.y * 128, n0 = blockIdx.x * 128;
    const int lr = tid >> 1, lc = (tid & 1) * 4;
    const float* Ag = A + (size_t)(m0 + lr) * lda + lc;
    const float* Bg = Bm + (size_t)(n0 + lr) * ldb + lc;
    const int ty = tid >> 4, tx = tid & 15;

    float acc[8][8];
#pragma unroll
    for (int i = 0; i < 8; i++)
#pragma unroll
        for (int j = 0; j < 8; j++) acc[i][j] = 0.f;

    for (int k0 = 0; k0 < K; k0 += 8) {
#pragma unroll
        for (int j = 0; j < 4; j++) {
            int kk = k0 + lc + j;
            As[lc + j][lr] = (kk < K) ? Ag[k0 + j] : 0.f;
            Bs[lc + j][lr] = (kk < K) ? Bg[k0 + j] : 0.f;
        }
        __syncthreads();
#pragma unroll
        for (int k = 0; k < 8; k++) {
            float4 a0 = *(const float4*)&As[k][ty * 4];
            float4 a1 = *(const float4*)&As[k][64 + ty * 4];
            float4 b0 = *(const float4*)&Bs[k][tx * 4];
            float4 b1 = *(const float4*)&Bs[k][64 + tx * 4];
            float af[8] = {a0.x, a0.y, a0.z, a0.w, a1.x, a1.y, a1.z, a1.w};
            float bf[8] = {b0.x, b0.y, b0.z, b0.w, b1.x, b1.y, b1.z, b1.w};
#pragma unroll
            for (int i = 0; i < 8; i++)
#pragma unroll
                for (int j = 0; j < 8; j++) acc[i][j] += af[i] * bf[j];
        }
        __syncthreads();
    }
#pragma unroll
    for (int i = 0; i < 8; i++) {
        int mg = m0 + ((i < 4) ? (ty * 4 + i) : (64 + ty * 4 + (i - 4)));
        size_t rowoff = (size_t)mg * ldc;
#pragma unroll
        for (int j = 0; j < 8; j++) {
            int ng = n0 + ((j < 4) ? (tx * 4 + j) : (64 + tx * 4 + (j - 4)));
            float v = acc[i][j] + bias[ng];
            v = v > 0.f ? v : 0.f;
            C[rowoff + ng] = v;
            Ch[rowoff + ng] = __float2half_rn(v);
        }
    }
}

// ==================== launch ====================
extern "C" void kernel_launch(void* const* d_in, const int* in_sizes, int n_in,
                              void* d_out, int out_size) {
    const float* dense   = (const float*)d_in[0];
    const void*  indices = d_in[1];
    const void*  offsets = d_in[2];
    const float* emb     = (const float*)d_in[3];
    const float* bW0 = (const float*)d_in[4];  const float* bb0 = (const float*)d_in[5];
    const float* bW1 = (const float*)d_in[6];  const float* bb1 = (const float*)d_in[7];
    const float* bW2 = (const float*)d_in[8];  const float* bb2 = (const float*)d_in[9];
    const float* dcnW = (const float*)d_in[10];
    const float* dcnV = (const float*)d_in[11];
    const float* dcnb = (const float*)d_in[12];
    const float* tW0 = (const float*)d_in[13]; const float* tb0 = (const float*)d_in[14];
    const float* tW1 = (const float*)d_in[15]; const float* tb1 = (const float*)d_in[16];
    const float* tW2 = (const float*)d_in[17]; const float* tb2 = (const float*)d_in[18];
    const float* tW3 = (const float*)d_in[19]; const float* tb3 = (const float*)d_in[20];

    float *bot0, *comb, *xl;
    __half *actA, *z0h, *z1h, *xvh, *wV, *wW, *wT0, *wT1, *wT2, *wB1, *wB2;
    cudaGetSymbolAddress((void**)&bot0, g_bot0);
    cudaGetSymbolAddress((void**)&comb, g_comb);
    cudaGetSymbolAddress((void**)&xl,   g_xl);
    cudaGetSymbolAddress((void**)&actA, g_actA);
    cudaGetSymbolAddress((void**)&z0h,  g_z0h);
    cudaGetSymbolAddress((void**)&z1h,  g_z1h);
    cudaGetSymbolAddress((void**)&xvh,  g_xvh);
    cudaGetSymbolAddress((void**)&wV,   g_wV);
    cudaGetSymbolAddress((void**)&wW,   g_wW);
    cudaGetSymbolAddress((void**)&wT0,  g_wT0);
    cudaGetSymbolAddress((void**)&wT1,  g_wT1);
    cudaGetSymbolAddress((void**)&wT2,  g_wT2);
    cudaGetSymbolAddress((void**)&wB1,  g_wB1);
    cudaGetSymbolAddress((void**)&wB2,  g_wB2);

    const int dynsmem = STAGES * 32768 + 1024;
    cudaFuncSetAttribute(tc_gemm<2>, cudaFuncAttributeMaxDynamicSharedMemorySize, dynsmem);
    cudaFuncSetAttribute(tc_gemm<3>, cudaFuncAttributeMaxDynamicSharedMemorySize, dynsmem);
    cudaFuncSetAttribute(tc_gemm<4>, cudaFuncAttributeMaxDynamicSharedMemorySize, dynsmem);
    cudaFuncSetAttribute(tc_gemm<6>, cudaFuncAttributeMaxDynamicSharedMemorySize, dynsmem);
    cudaFuncSetAttribute(tc_gemm<7>, cudaFuncAttributeMaxDynamicSharedMemorySize, dynsmem);

    // --- fused weight conversion + dtype detect + out init
    ConvArgs ca;
    ca.src[0] = dcnV; ca.dst[0] = wV;  ca.n[0] = 3 * LOWR * FIN;
    ca.src[1] = dcnW; ca.dst[1] = wW;  ca.n[1] = 3 * FIN * LOWR;
    ca.src[2] = tW0;  ca.dst[2] = wT0; ca.n[2] = 1024 * FIN;
    ca.src[3] = tW1;  ca.dst[3] = wT1; ca.n[3] = 1024 * 1024;
    ca.src[4] = tW2;  ca.dst[4] = wT2; ca.n[4] = 512 * 1024;
    ca.src[5] = bW1;  ca.dst[5] = wB1; ca.n[5] = 256 * 512;
    ca.src[6] = bW2;  ca.dst[6] = wB2; ca.n[6] = 128 * 256;
    ca.total = ca.n[0] + ca.n[1] + ca.n[2] + ca.n[3] + ca.n[4] + ca.n[5] + ca.n[6];
    ca.offwords = (const unsigned*)offsets;
    ca.offn = in_sizes[2];
    ca.out = (float*)d_out;
    ca.b3 = tb3;
    convall_kernel<<<2048, 256>>>(ca);

    // --- bottom MLP: 13 -> 512 (fp32+fp16) -> 256 (fp16 tc) -> 128 (tc, EPI7)
    sgemm_l1<<<dim3(4, 32), 256>>>(dense, 13, bW0, 13, bb0, bot0, 512, 13, z0h);
    tc_gemm<4><<<dim3(2, 32), 128, dynsmem>>>(
        z0h, wB1, bb1, nullptr, 0, z1h, 256, 512, nullptr, nullptr);
    tc_gemm<7><<<dim3(1, 32), 128, dynsmem>>>(
        z1h, wB2, bb2, comb, FIN, actA, FIN, 256, nullptr, nullptr);

    // --- embedding-bag pooling into comb + actA slots 1..26
    pool_kernel<<<(NTAB * BATCH) / 8, 256>>>(indices, offsets, emb, comb, actA);

    // --- low-rank DCN (fp16 GEMMs; x_l master in fp32, fp16 feed in actA)
    for (int l = 0; l < 3; l++) {
        const float* xlin = (l == 0) ? comb : xl;
        tc_gemm<3><<<dim3(LOWR / 128, 32), 128, dynsmem>>>(
            actA, wV + (size_t)l * LOWR * FIN, nullptr, nullptr, 0,
            xvh, LOWR, FIN, nullptr, nullptr);
        tc_gemm<2><<<dim3(FIN / 128, 32), 128, dynsmem>>>(
            xvh, wW + (size_t)l * FIN * LOWR, dcnb + (size_t)l * FIN, xl, FIN,
            actA, FIN, LOWR, comb, xlin);
    }

    // --- top MLP: 3456 -> 1024 -> 1024 -> 512 (relu) -> 1 (fused dot)
    tc_gemm<4><<<dim3(8, 32), 128, dynsmem>>>(
        actA, wT0, tb0, nullptr, 0, z0h, 1024, FIN, nullptr, nullptr);
    tc_gemm<4><<<dim3(8, 32), 128, dynsmem>>>(
        z0h, wT1, tb1, nullptr, 0, z1h, 1024, 1024, nullptr, nullptr);
    tc_gemm<6><<<dim3(4, 32), 128, dynsmem>>>(
        z1h, wT2, tb2, (float*)d_out, 0, nullptr, 0, 1024, tW3, nullptr);
}

// round 13
// speedup vs baseline: 7.8008x; 1.0458x over previous
#include <cuda_runtime.h>
#include <cuda_fp16.h>
#include <cstdint>
#include <cstddef>

// ---------------- problem constants ----------------
#define BATCH   4096
#define NTAB    26
#define DEMB    128
#define NTPER   81920
#define EROWS   100000
#define FIN     3456
#define LOWR    512
#define STAGES  3

// ---------------- scratch (device globals; no runtime alloc) ----------------
__device__ float  g_comb[BATCH * FIN];     // combined features (fp32, immutable)
__device__ float  g_xl  [BATCH * FIN];     // DCN running state (fp32 master)
__device__ int    g_is64;
__device__ __half g_actA[BATCH * FIN];     // fp16 copy of current DCN input
__device__ __half g_z0h [BATCH * 1024];    // also bot0h (disjoint in time)
__device__ __half g_z1h [BATCH * 1024];    // also bot1h
__device__ __half g_xvh [BATCH * LOWR];
// dedicated fp16 weight buffers
__device__ __half g_wV [3 * LOWR * FIN];
__device__ __half g_wW [3 * FIN * LOWR];
__device__ __half g_wT0[1024 * FIN];
__device__ __half g_wT1[1024 * 1024];
__device__ __half g_wT2[512 * 1024];
__device__ __half g_wB1[256 * 512];
__device__ __half g_wB2[128 * 256];

// ==================== PTX helpers ====================
__device__ __forceinline__ uint32_t smem_u32(const void* p) {
    uint32_t a;
    asm("{ .reg .u64 t; cvta.to.shared.u64 t, %1; cvt.u32.u64 %0, t; }" : "=r"(a) : "l"(p));
    return a;
}
#define SWZ(x) ((x) ^ (((x) >> 3) & 0x70))

__device__ __forceinline__ void cp16(uint32_t dst, const void* src) {
    asm volatile("cp.async.cg.shared.global [%0], [%1], 16;" :: "r"(dst), "l"(src) : "memory");
}
__device__ __forceinline__ void cp_commit() { asm volatile("cp.async.commit_group;" ::: "memory"); }
template<int N> __device__ __forceinline__ void cp_wait() {
    asm volatile("cp.async.wait_group %0;" :: "n"(N) : "memory");
}
__device__ __forceinline__ void ldm_x4(uint32_t& r0, uint32_t& r1, uint32_t& r2, uint32_t& r3,
                                       uint32_t addr) {
    asm volatile("ldmatrix.sync.aligned.m8n8.x4.shared.b16 {%0,%1,%2,%3}, [%4];"
                 : "=r"(r0), "=r"(r1), "=r"(r2), "=r"(r3) : "r"(addr));
}
__device__ __forceinline__ void mma16816(float* c, const uint32_t* a, uint32_t b0, uint32_t b1) {
    asm volatile(
        "mma.sync.aligned.m16n8k16.row.col.f32.f16.f16.f32 "
        "{%0,%1,%2,%3}, {%4,%5,%6,%7}, {%8,%9}, {%0,%1,%2,%3};"
        : "+f"(c[0]), "+f"(c[1]), "+f"(c[2]), "+f"(c[3])
        : "r"(a[0]), "r"(a[1]), "r"(a[2]), "r"(a[3]), "r"(b0), "r"(b1));
}

__device__ __forceinline__ void half_store2(__half* __restrict__ p, size_t o,
                                            float v0, float v1) {
    __half2 hh; hh.x = __float2half_rn(v0); hh.y = __float2half_rn(v1);
    *(__half2*)(p + o) = hh;
}

// ==================== dtype detection (int64 vs int32) ====================
__global__ void detect_kernel(const unsigned* __restrict__ words, int n_elems) {
    __shared__ unsigned red;
    if (threadIdx.x == 0) red = 0u;
    __syncthreads();
    int n = n_elems < 8192 ? n_elems : 8192;
    unsigned acc = 0u;
    for (int i = 1 + 2 * (int)threadIdx.x; i < n; i += 2 * (int)blockDim.x) acc |= words[i];
    if (acc) atomicOr(&red, 1u);
    __syncthreads();
    if (threadIdx.x == 0) g_is64 = (red == 0u) ? 1 : 0;
}

// ==================== fused weight conversion + out-init ===================
struct ConvArgs {
    const float* src[7];
    __half*      dst[7];
    int          n[7];
    int          total;
    float*       out;       // d_out, init to b3[0]
    const float* b3;
};

__global__ void conv_kernel(ConvArgs a) {
    if (blockIdx.x == 0) {   // init final output to bias b3
        float b = a.b3[0];
        for (int i = threadIdx.x; i < BATCH; i += blockDim.x) a.out[i] = b;
    }
    for (int gid = blockIdx.x * blockDim.x + threadIdx.x; gid < a.total;
         gid += gridDim.x * blockDim.x) {
        int i = gid;
#pragma unroll
        for (int s = 0; s < 7; s++) {
            if (i < a.n[s]) { a.dst[s][i] = __float2half_rn(a.src[s][i]); break; }
            i -= a.n[s];
        }
    }
}

// ==================== embedding-bag pooling: one warp per (table, bag) ======
template<typename IT>
__device__ __forceinline__ float4 pool_rows(const IT* __restrict__ idx,
                                            const float* __restrict__ tab,
                                            long long lo, long long hi, int lane) {
    float4 acc = make_float4(0.f, 0.f, 0.f, 0.f);
    long long i = lo;
    for (; i + 4 <= hi; i += 4) {
        size_t r0 = (size_t)idx[i],     r1 = (size_t)idx[i + 1];
        size_t r2 = (size_t)idx[i + 2], r3 = (size_t)idx[i + 3];
        float4 v0 = *(const float4*)(tab + r0 * DEMB + lane * 4);
        float4 v1 = *(const float4*)(tab + r1 * DEMB + lane * 4);
        float4 v2 = *(const float4*)(tab + r2 * DEMB + lane * 4);
        float4 v3 = *(const float4*)(tab + r3 * DEMB + lane * 4);
        acc.x += v0.x + v1.x + v2.x + v3.x;
        acc.y += v0.y + v1.y + v2.y + v3.y;
        acc.z += v0.z + v1.z + v2.z + v3.z;
        acc.w += v0.w + v1.w + v2.w + v3.w;
    }
    for (; i < hi; ++i) {
        float4 v = *(const float4*)(tab + (size_t)idx[i] * DEMB + lane * 4);
        acc.x += v.x; acc.y += v.y; acc.z += v.z; acc.w += v.w;
    }
    return acc;
}

__global__ void pool_kernel(const void* __restrict__ idxp,
                            const void* __restrict__ offp,
                            const float* __restrict__ tables,
                            float* __restrict__ comb,
                            __half* __restrict__ actA) {
    int wg   = (blockIdx.x * blockDim.x + threadIdx.x) >> 5;
    int lane = threadIdx.x & 31;
    if (wg >= NTAB * BATCH) return;
    int t = wg / BATCH;
    int b = wg - t * BATCH;

    const int is64 = g_is64;
    long long lo, hi;
    if (is64) {
        const long long* off = (const long long*)offp + (size_t)t * BATCH;
        lo = (b == 0) ? 0 : off[b];
        hi = (b == BATCH - 1) ? (long long)NTPER : off[b + 1];
    } else {
        const int* off = (const int*)offp + (size_t)t * BATCH;
        lo = (b == 0) ? 0 : (long long)off[b];
        hi = (b == BATCH - 1) ? (long long)NTPER : (long long)off[b + 1];
    }

    const float* tab = tables + (size_t)t * EROWS * DEMB;
    float4 acc;
    if (is64) acc = pool_rows((const long long*)idxp + (size_t)t * NTPER, tab, lo, hi, lane);
    else      acc = pool_rows((const int*)idxp + (size_t)t * NTPER, tab, lo, hi, lane);

    const int col = (t + 1) * DEMB + lane * 4;
    *(float4*)(comb + (size_t)b * FIN + col) = acc;
    size_t o = (size_t)b * FIN + col;
    half_store2(actA, o,     acc.x, acc.y);
    half_store2(actA, o + 2, acc.z, acc.w);
}

// ==================== mma.sync fp16 GEMM: C = A[M,K] * B[N,K]^T ============
// CTA tile 128x128, BK=64, 3-stage cp.async, 2 CTA/SM.
// 128 threads = 4 warps in 2(m) x 2(n); warp tile 64x64 (MMA:LDSM = 4).
// EPI: 2 = DCN: v = aux*(acc+bias)+xlin -> fp32 Cf AND fp16 Ch
//      3 = fp16 Ch raw
//      4 = relu(acc+bias) -> fp16 Ch
//      6 = relu(acc+bias), dot with w3 (aux), atomicAdd into Cf (pre-init b3)
//      7 = relu(acc+bias) -> fp32 Cf AND fp16 Ch
__device__ __forceinline__ void load_stage(uint32_t base, int st, int kb,
                                           const char* Ab, const char* Bb,
                                           size_t rstride, int row_r, int c16) {
    uint32_t sA = base + (uint32_t)st * 32768u;
    uint32_t sB = sA + 16384u;
    size_t koff = (size_t)kb * 128 + c16;
#pragma unroll
    for (int j = 0; j < 8; j++) {
        int row = j * 16 + row_r;
        uint32_t so = SWZ((uint32_t)(row * 128 + c16));
        cp16(sA + so, Ab + (size_t)row * rstride + koff);
        cp16(sB + so, Bb + (size_t)row * rstride + koff);
    }
}

template<int EPI>
__global__ void __launch_bounds__(128, 2)
tc_gemm(const __half* __restrict__ A, const __half* __restrict__ B,
        const float* __restrict__ bias,
        float* __restrict__ Cf, int ldc,
        __half* __restrict__ Ch, int ldh, int K,
        const float* __restrict__ aux, const float* __restrict__ xlin) {
    extern __shared__ char dsm[];
    const uint32_t base = (smem_u32(dsm) + 1023u) & ~1023u;

    const int tid  = threadIdx.x;
    const int wid  = tid >> 5, lane = tid & 31;
    const int wm   = wid & 1;        // 2 m-warps * 64 rows
    const int wn   = wid >> 1;       // 2 n-warps * 64 cols
    const int m0   = blockIdx.y * 128, n0 = blockIdx.x * 128;
    const int row_r = tid >> 3, c16 = (tid & 7) * 16;

    const int NKB = K >> 6;
    const char* Ab = (const char*)A + (size_t)m0 * K * 2;
    const char* Bb = (const char*)B + (size_t)n0 * K * 2;
    const size_t rstride = (size_t)K * 2;

    const int ar = lane & 15;
    const int ac = (lane >> 4) * 16;
    const int br = lane & 7;
    const int bn = ((lane >> 4) & 1) * 8;
    const int bc = ((lane >> 3) & 1) * 16;

    float acc[4][8][4];
#pragma unroll
    for (int i = 0; i < 4; i++)
#pragma unroll
        for (int j = 0; j < 8; j++)
#pragma unroll
            for (int e = 0; e < 4; e++) acc[i][j][e] = 0.f;

    for (int s = 0; s < STAGES - 1 && s < NKB; s++) {
        load_stage(base, s, s, Ab, Bb, rstride, row_r, c16);
        cp_commit();
    }

    for (int kb = 0; kb < NKB; kb++) {
        const int st = kb % STAGES;
        cp_wait<STAGES - 2>();
        __syncthreads();

        const uint32_t sA = base + (uint32_t)st * 32768u;
        const uint32_t sB = sA + 16384u;
#pragma unroll
        for (int ks = 0; ks < 4; ks++) {
            const int kbyte = ks * 32;
            uint32_t a[4][4];
#pragma unroll
            for (int fm = 0; fm < 4; fm++) {
                uint32_t ad = sA + SWZ((uint32_t)((wm * 64 + fm * 16 + ar) * 128 + kbyte + ac));
                ldm_x4(a[fm][0], a[fm][1], a[fm][2], a[fm][3], ad);
            }
#pragma unroll
            for (int g = 0; g < 4; g++) {
                uint32_t b0, b1, b2, b3;
                uint32_t bd = sB + SWZ((uint32_t)((wn * 64 + g * 16 + bn + br) * 128 + kbyte + bc));
                ldm_x4(b0, b1, b2, b3, bd);
#pragma unroll
                for (int fm = 0; fm < 4; fm++) {
                    mma16816(acc[fm][2 * g],     a[fm], b0, b1);
                    mma16816(acc[fm][2 * g + 1], a[fm], b2, b3);
                }
            }
        }
        // slot refilled below was consumed last iteration; fenced by the
        // post-wait __syncthreads() above.
        const int nk = kb + STAGES - 1;
        if (nk < NKB)
            load_stage(base, nk % STAGES, nk, Ab, Bb, rstride, row_r, c16);
        cp_commit();
    }

    // ---------------- epilogue (register accumulators) ----------------
    const int er = lane >> 2;
    const int ec = (lane & 3) * 2;
    float fs[4][2];
    if (EPI == 6) {
#pragma unroll
        for (int i = 0; i < 4; i++) { fs[i][0] = 0.f; fs[i][1] = 0.f; }
    }
#pragma unroll
    for (int fm = 0; fm < 4; fm++) {
#pragma unroll
        for (int fn = 0; fn < 8; fn++) {
            const int ng = n0 + wn * 64 + fn * 8 + ec;
#pragma unroll
            for (int rr = 0; rr < 2; rr++) {
                const int m = m0 + wm * 64 + fm * 16 + er + rr * 8;
                float v0 = acc[fm][fn][rr * 2 + 0];
                float v1 = acc[fm][fn][rr * 2 + 1];
                if (EPI == 4 || EPI == 6 || EPI == 7) {
                    v0 += bias[ng];     v0 = v0 > 0.f ? v0 : 0.f;
                    v1 += bias[ng + 1]; v1 = v1 > 0.f ? v1 : 0.f;
                }
                if (EPI == 2) {
                    size_t o = (size_t)m * ldc + ng;
                    float2 cb = *(const float2*)(aux + o);
                    float2 xb = *(const float2*)(xlin + o);
                    v0 = cb.x * (v0 + bias[ng])     + xb.x;
                    v1 = cb.y * (v1 + bias[ng + 1]) + xb.y;
                    *(float2*)(Cf + o) = make_float2(v0, v1);
                }
                if (EPI == 7)
                    *(float2*)(Cf + (size_t)m * ldc + ng) = make_float2(v0, v1);
                if (EPI == 6)
                    fs[fm][rr] += v0 * aux[ng] + v1 * aux[ng + 1];
                if (EPI == 2 || EPI == 3 || EPI == 4 || EPI == 7)
                    half_store2(Ch, (size_t)m * ldh + ng, v0, v1);
            }
        }
    }
    if (EPI == 6) {
#pragma unroll
        for (int fm = 0; fm < 4; fm++)
#pragma unroll
            for (int rr = 0; rr < 2; rr++) {
                float s = fs[fm][rr];
                s += __shfl_xor_sync(0xffffffffu, s, 1);
                s += __shfl_xor_sync(0xffffffffu, s, 2);
                if ((lane & 3) == 0) {
                    const int m = m0 + wm * 64 + fm * 16 + er + rr * 8;
                    atomicAdd(&Cf[m], s);
                }
            }
    }
}

// ==================== fp32 SGEMM (bottom layer 1 only, K=13) ===============
// relu -> fp16 Ch only (fp32 copy is dead downstream).
__global__ void __launch_bounds__(256, 2)
sgemm_l1(const float* __restrict__ A, int lda,
         const float* __restrict__ Bm, int ldb,
         const float* __restrict__ bias,
         int ldc, int K,
         __half* __restrict__ Ch) {
    __shared__ __align__(16) float As[8][128];
    __shared__ __align__(16) float Bs[8][128];
    const int tid = threadIdx.x;
    const int m0 = blockIdx.y * 128, n0 = blockIdx.x * 128;
    const int lr = tid >> 1, lc = (tid & 1) * 4;
    const float* Ag = A + (size_t)(m0 + lr) * lda + lc;
    const float* Bg = Bm + (size_t)(n0 + lr) * ldb + lc;
    const int ty = tid >> 4, tx = tid & 15;

    float acc[8][8];
#pragma unroll
    for (int i = 0; i < 8; i++)
#pragma unroll
        for (int j = 0; j < 8; j++) acc[i][j] = 0.f;

    for (int k0 = 0; k0 < K; k0 += 8) {
#pragma unroll
        for (int j = 0; j < 4; j++) {
            int kk = k0 + lc + j;
            As[lc + j][lr] = (kk < K) ? Ag[k0 + j] : 0.f;
            Bs[lc + j][lr] = (kk < K) ? Bg[k0 + j] : 0.f;
        }
        __syncthreads();
#pragma unroll
        for (int k = 0; k < 8; k++) {
            float4 a0 = *(const float4*)&As[k][ty * 4];
            float4 a1 = *(const float4*)&As[k][64 + ty * 4];
            float4 b0 = *(const float4*)&Bs[k][tx * 4];
            float4 b1 = *(const float4*)&Bs[k][64 + tx * 4];
            float af[8] = {a0.x, a0.y, a0.z, a0.w, a1.x, a1.y, a1.z, a1.w};
            float bf[8] = {b0.x, b0.y, b0.z, b0.w, b1.x, b1.y, b1.z, b1.w};
#pragma unroll
            for (int i = 0; i < 8; i++)
#pragma unroll
                for (int j = 0; j < 8; j++) acc[i][j] += af[i] * bf[j];
        }
        __syncthreads();
    }
#pragma unroll
    for (int i = 0; i < 8; i++) {
        int mg = m0 + ((i < 4) ? (ty * 4 + i) : (64 + ty * 4 + (i - 4)));
        size_t rowoff = (size_t)mg * ldc;
#pragma unroll
        for (int j = 0; j < 8; j++) {
            int ng = n0 + ((j < 4) ? (tx * 4 + j) : (64 + tx * 4 + (j - 4)));
            float v = acc[i][j] + bias[ng];
            v = v > 0.f ? v : 0.f;
            Ch[rowoff + ng] = __float2half_rn(v);
        }
    }
}

// ==================== launch ====================
extern "C" void kernel_launch(void* const* d_in, const int* in_sizes, int n_in,
                              void* d_out, int out_size) {
    const float* dense   = (const float*)d_in[0];
    const void*  indices = d_in[1];
    const void*  offsets = d_in[2];
    const float* emb     = (const float*)d_in[3];
    const float* bW0 = (const float*)d_in[4];  const float* bb0 = (const float*)d_in[5];
    const float* bW1 = (const float*)d_in[6];  const float* bb1 = (const float*)d_in[7];
    const float* bW2 = (const float*)d_in[8];  const float* bb2 = (const float*)d_in[9];
    const float* dcnW = (const float*)d_in[10];
    const float* dcnV = (const float*)d_in[11];
    const float* dcnb = (const float*)d_in[12];
    const float* tW0 = (const float*)d_in[13]; const float* tb0 = (const float*)d_in[14];
    const float* tW1 = (const float*)d_in[15]; const float* tb1 = (const float*)d_in[16];
    const float* tW2 = (const float*)d_in[17]; const float* tb2 = (const float*)d_in[18];
    const float* tW3 = (const float*)d_in[19]; const float* tb3 = (const float*)d_in[20];

    float *comb, *xl;
    __half *actA, *z0h, *z1h, *xvh, *wV, *wW, *wT0, *wT1, *wT2, *wB1, *wB2;
    cudaGetSymbolAddress((void**)&comb, g_comb);
    cudaGetSymbolAddress((void**)&xl,   g_xl);
    cudaGetSymbolAddress((void**)&actA, g_actA);
    cudaGetSymbolAddress((void**)&z0h,  g_z0h);
    cudaGetSymbolAddress((void**)&z1h,  g_z1h);
    cudaGetSymbolAddress((void**)&xvh,  g_xvh);
    cudaGetSymbolAddress((void**)&wV,   g_wV);
    cudaGetSymbolAddress((void**)&wW,   g_wW);
    cudaGetSymbolAddress((void**)&wT0,  g_wT0);
    cudaGetSymbolAddress((void**)&wT1,  g_wT1);
    cudaGetSymbolAddress((void**)&wT2,  g_wT2);
    cudaGetSymbolAddress((void**)&wB1,  g_wB1);
    cudaGetSymbolAddress((void**)&wB2,  g_wB2);

    const int dynsmem = STAGES * 32768 + 1024;
    cudaFuncSetAttribute(tc_gemm<2>, cudaFuncAttributeMaxDynamicSharedMemorySize, dynsmem);
    cudaFuncSetAttribute(tc_gemm<3>, cudaFuncAttributeMaxDynamicSharedMemorySize, dynsmem);
    cudaFuncSetAttribute(tc_gemm<4>, cudaFuncAttributeMaxDynamicSharedMemorySize, dynsmem);
    cudaFuncSetAttribute(tc_gemm<6>, cudaFuncAttributeMaxDynamicSharedMemorySize, dynsmem);
    cudaFuncSetAttribute(tc_gemm<7>, cudaFuncAttributeMaxDynamicSharedMemorySize, dynsmem);

    // --- side stream for the compute chain (conversion + bottom MLP),
    //     overlapped with the DRAM-bound pooling on the main stream.
    cudaStream_t s1;
    cudaEvent_t evFork, evJoin;
    cudaStreamCreateWithFlags(&s1, cudaStreamNonBlocking);
    cudaEventCreateWithFlags(&evFork, cudaEventDisableTiming);
    cudaEventCreateWithFlags(&evJoin, cudaEventDisableTiming);

    cudaEventRecord(evFork, 0);
    cudaStreamWaitEvent(s1, evFork, 0);

    // s1: weight conversion + out-init, then bottom MLP into comb/actA cols 0-127
    ConvArgs ca;
    ca.src[0] = dcnV; ca.dst[0] = wV;  ca.n[0] = 3 * LOWR * FIN;
    ca.src[1] = dcnW; ca.dst[1] = wW;  ca.n[1] = 3 * FIN * LOWR;
    ca.src[2] = tW0;  ca.dst[2] = wT0; ca.n[2] = 1024 * FIN;
    ca.src[3] = tW1;  ca.dst[3] = wT1; ca.n[3] = 1024 * 1024;
    ca.src[4] = tW2;  ca.dst[4] = wT2; ca.n[4] = 512 * 1024;
    ca.src[5] = bW1;  ca.dst[5] = wB1; ca.n[5] = 256 * 512;
    ca.src[6] = bW2;  ca.dst[6] = wB2; ca.n[6] = 128 * 256;
    ca.total = ca.n[0] + ca.n[1] + ca.n[2] + ca.n[3] + ca.n[4] + ca.n[5] + ca.n[6];
    ca.out = (float*)d_out;
    ca.b3 = tb3;
    conv_kernel<<<2048, 256, 0, s1>>>(ca);
    sgemm_l1<<<dim3(4, 32), 256, 0, s1>>>(dense, 13, bW0, 13, bb0, 512, 13, z0h);
    tc_gemm<4><<<dim3(2, 32), 128, dynsmem, s1>>>(
        z0h, wB1, bb1, nullptr, 0, z1h, 256, 512, nullptr, nullptr);
    tc_gemm<7><<<dim3(1, 32), 128, dynsmem, s1>>>(
        z1h, wB2, bb2, comb, FIN, actA, FIN, 256, nullptr, nullptr);
    cudaEventRecord(evJoin, s1);

    // main stream: dtype detect + pooling into comb/actA cols 128..3455
    detect_kernel<<<1, 256>>>((const unsigned*)offsets, in_sizes[2]);
    pool_kernel<<<(NTAB * BATCH) / 8, 256>>>(indices, offsets, emb, comb, actA);

    // join: DCN needs full actA/comb and converted weights
    cudaStreamWaitEvent(0, evJoin, 0);

    // --- low-rank DCN (fp16 GEMMs; x_l master in fp32, fp16 feed in actA)
    for (int l = 0; l < 3; l++) {
        const float* xlin = (l == 0) ? comb : xl;
        tc_gemm<3><<<dim3(LOWR / 128, 32), 128, dynsmem>>>(
            actA, wV + (size_t)l * LOWR * FIN, nullptr, nullptr, 0,
            xvh, LOWR, FIN, nullptr, nullptr);
        tc_gemm<2><<<dim3(FIN / 128, 32), 128, dynsmem>>>(
            xvh, wW + (size_t)l * FIN * LOWR, dcnb + (size_t)l * FIN, xl, FIN,
            actA, FIN, LOWR, comb, xlin);
    }

    // --- top MLP: 3456 -> 1024 -> 1024 -> 512 (relu) -> 1 (fused dot)
    tc_gemm<4><<<dim3(8, 32), 128, dynsmem>>>(
        actA, wT0, tb0, nullptr, 0, z0h, 1024, FIN, nullptr, nullptr);
    tc_gemm<4><<<dim3(8, 32), 128, dynsmem>>>(
        z0h, wT1, tb1, nullptr, 0, z1h, 1024, 1024, nullptr, nullptr);
    tc_gemm<6><<<dim3(4, 32), 128, dynsmem>>>(
        z1h, wT2, tb2, (float*)d_out, 0, nullptr, 0, 1024, tW3, nullptr);
}

// round 14
// speedup vs baseline: 7.8577x; 1.0073x over previous
#include <cuda_runtime.h>
#include <cuda_fp16.h>
#include <cstdint>
#include <cstddef>

// ---------------- problem constants ----------------
#define BATCH   4096
#define NTAB    26
#define DEMB    128
#define NTPER   81920
#define EROWS   100000
#define FIN     3456
#define LOWR    512
#define STAGES  3

// ---------------- scratch (device globals; no runtime alloc) ----------------
__device__ float  g_comb[BATCH * FIN];     // combined features (fp32, immutable)
__device__ float  g_xl  [BATCH * FIN];     // DCN running state (fp32 master)
__device__ int    g_is64;
__device__ __half g_actA[BATCH * FIN];     // fp16 copy of current DCN input
__device__ __half g_z0h [BATCH * 1024];    // also bot0h (disjoint in time)
__device__ __half g_z1h [BATCH * 1024];    // also bot1h
__device__ __half g_xvh [BATCH * LOWR];
// dedicated fp16 weight buffers
__device__ __half g_wV [3 * LOWR * FIN];
__device__ __half g_wW [3 * FIN * LOWR];
__device__ __half g_wT0[1024 * FIN];
__device__ __half g_wT1[1024 * 1024];
__device__ __half g_wT2[512 * 1024];
__device__ __half g_wB1[256 * 512];
__device__ __half g_wB2[128 * 256];

// ==================== PTX helpers ====================
__device__ __forceinline__ uint32_t smem_u32(const void* p) {
    uint32_t a;
    asm("{ .reg .u64 t; cvta.to.shared.u64 t, %1; cvt.u32.u64 %0, t; }" : "=r"(a) : "l"(p));
    return a;
}
#define SWZ(x) ((x) ^ (((x) >> 3) & 0x70))

__device__ __forceinline__ void cp16(uint32_t dst, const void* src) {
    asm volatile("cp.async.cg.shared.global [%0], [%1], 16;" :: "r"(dst), "l"(src) : "memory");
}
__device__ __forceinline__ void cp_commit() { asm volatile("cp.async.commit_group;" ::: "memory"); }
template<int N> __device__ __forceinline__ void cp_wait() {
    asm volatile("cp.async.wait_group %0;" :: "n"(N) : "memory");
}
__device__ __forceinline__ void ldm_x4(uint32_t& r0, uint32_t& r1, uint32_t& r2, uint32_t& r3,
                                       uint32_t addr) {
    asm volatile("ldmatrix.sync.aligned.m8n8.x4.shared.b16 {%0,%1,%2,%3}, [%4];"
                 : "=r"(r0), "=r"(r1), "=r"(r2), "=r"(r3) : "r"(addr));
}
__device__ __forceinline__ void mma16816(float* c, const uint32_t* a, uint32_t b0, uint32_t b1) {
    asm volatile(
        "mma.sync.aligned.m16n8k16.row.col.f32.f16.f16.f32 "
        "{%0,%1,%2,%3}, {%4,%5,%6,%7}, {%8,%9}, {%0,%1,%2,%3};"
        : "+f"(c[0]), "+f"(c[1]), "+f"(c[2]), "+f"(c[3])
        : "r"(a[0]), "r"(a[1]), "r"(a[2]), "r"(a[3]), "r"(b0), "r"(b1));
}

__device__ __forceinline__ void half_store2(__half* __restrict__ p, size_t o,
                                            float v0, float v1) {
    __half2 hh; hh.x = __float2half_rn(v0); hh.y = __float2half_rn(v1);
    *(__half2*)(p + o) = hh;
}

// ==================== dtype detection (int64 vs int32) ====================
__global__ void detect_kernel(const unsigned* __restrict__ words, int n_elems) {
    __shared__ unsigned red;
    if (threadIdx.x == 0) red = 0u;
    __syncthreads();
    int n = n_elems < 8192 ? n_elems : 8192;
    unsigned acc = 0u;
    for (int i = 1 + 2 * (int)threadIdx.x; i < n; i += 2 * (int)blockDim.x) acc |= words[i];
    if (acc) atomicOr(&red, 1u);
    __syncthreads();
    if (threadIdx.x == 0) g_is64 = (red == 0u) ? 1 : 0;
}

// ==================== fused weight conversion + out-init ===================
struct ConvArgs {
    const float* src[7];
    __half*      dst[7];
    int          n[7];
    int          total;
    float*       out;       // d_out, init to b3[0]
    const float* b3;
};

__global__ void conv_kernel(ConvArgs a) {
    if (blockIdx.x == 0) {   // init final output to bias b3
        float b = a.b3[0];
        for (int i = threadIdx.x; i < BATCH; i += blockDim.x) a.out[i] = b;
    }
    for (int gid = blockIdx.x * blockDim.x + threadIdx.x; gid < a.total;
         gid += gridDim.x * blockDim.x) {
        int i = gid;
#pragma unroll
        for (int s = 0; s < 7; s++) {
            if (i < a.n[s]) { a.dst[s][i] = __float2half_rn(a.src[s][i]); break; }
            i -= a.n[s];
        }
    }
}

// ==================== embedding-bag pooling: one warp per (table, bag) ======
template<typename IT>
__device__ __forceinline__ float4 pool_rows(const IT* __restrict__ idx,
                                            const float* __restrict__ tab,
                                            long long lo, long long hi, int lane) {
    float4 acc = make_float4(0.f, 0.f, 0.f, 0.f);
    long long i = lo;
    for (; i + 4 <= hi; i += 4) {
        size_t r0 = (size_t)idx[i],     r1 = (size_t)idx[i + 1];
        size_t r2 = (size_t)idx[i + 2], r3 = (size_t)idx[i + 3];
        float4 v0 = *(const float4*)(tab + r0 * DEMB + lane * 4);
        float4 v1 = *(const float4*)(tab + r1 * DEMB + lane * 4);
        float4 v2 = *(const float4*)(tab + r2 * DEMB + lane * 4);
        float4 v3 = *(const float4*)(tab + r3 * DEMB + lane * 4);
        acc.x += v0.x + v1.x + v2.x + v3.x;
        acc.y += v0.y + v1.y + v2.y + v3.y;
        acc.z += v0.z + v1.z + v2.z + v3.z;
        acc.w += v0.w + v1.w + v2.w + v3.w;
    }
    for (; i < hi; ++i) {
        float4 v = *(const float4*)(tab + (size_t)idx[i] * DEMB + lane * 4);
        acc.x += v.x; acc.y += v.y; acc.z += v.z; acc.w += v.w;
    }
    return acc;
}

__global__ void pool_kernel(const void* __restrict__ idxp,
                            const void* __restrict__ offp,
                            const float* __restrict__ tables,
                            float* __restrict__ comb,
                            __half* __restrict__ actA) {
    int wg   = (blockIdx.x * blockDim.x + threadIdx.x) >> 5;
    int lane = threadIdx.x & 31;
    if (wg >= NTAB * BATCH) return;
    int t = wg / BATCH;
    int b = wg - t * BATCH;

    const int is64 = g_is64;
    long long lo, hi;
    if (is64) {
        const long long* off = (const long long*)offp + (size_t)t * BATCH;
        lo = (b == 0) ? 0 : off[b];
        hi = (b == BATCH - 1) ? (long long)NTPER : off[b + 1];
    } else {
        const int* off = (const int*)offp + (size_t)t * BATCH;
        lo = (b == 0) ? 0 : (long long)off[b];
        hi = (b == BATCH - 1) ? (long long)NTPER : (long long)off[b + 1];
    }

    const float* tab = tables + (size_t)t * EROWS * DEMB;
    float4 acc;
    if (is64) acc = pool_rows((const long long*)idxp + (size_t)t * NTPER, tab, lo, hi, lane);
    else      acc = pool_rows((const int*)idxp + (size_t)t * NTPER, tab, lo, hi, lane);

    const int col = (t + 1) * DEMB + lane * 4;
    *(float4*)(comb + (size_t)b * FIN + col) = acc;
    size_t o = (size_t)b * FIN + col;
    half_store2(actA, o,     acc.x, acc.y);
    half_store2(actA, o + 2, acc.z, acc.w);
}

// ==================== mma.sync fp16 GEMM: C = A[M,K] * B[N,K]^T ============
// CTA tile MT x 128 (MT in {128, 64}), BK=64, 3-stage cp.async.
// MT=128: 2 CTA/SM, warp tile 64x64.  MT=64: 3 CTA/SM, warp tile 32x64.
// 128 threads = 4 warps in 2(m) x 2(n).
// EPI: 2 = DCN: v = aux*(acc+bias)+xlin -> fp32 Cf AND fp16 Ch
//      3 = fp16 Ch raw
//      4 = relu(acc+bias) -> fp16 Ch
//      6 = relu(acc+bias), dot with w3 (aux), atomicAdd into Cf (pre-init b3)
//      7 = relu(acc+bias) -> fp32 Cf AND fp16 Ch
template<int MT>
__device__ __forceinline__ void load_stage(uint32_t base, int st, int kb,
                                           const char* Ab, const char* Bb,
                                           size_t rstride, int row_r, int c16) {
    const uint32_t stage_bytes = (uint32_t)(MT * 128 + 16384);
    uint32_t sA = base + (uint32_t)st * stage_bytes;
    uint32_t sB = sA + (uint32_t)(MT * 128);
    size_t koff = (size_t)kb * 128 + c16;
#pragma unroll
    for (int j = 0; j < MT / 16; j++) {
        int row = j * 16 + row_r;
        uint32_t so = SWZ((uint32_t)(row * 128 + c16));
        cp16(sA + so, Ab + (size_t)row * rstride + koff);
    }
#pragma unroll
    for (int j = 0; j < 8; j++) {
        int row = j * 16 + row_r;
        uint32_t so = SWZ((uint32_t)(row * 128 + c16));
        cp16(sB + so, Bb + (size_t)row * rstride + koff);
    }
}

template<int EPI, int MT>
__global__ void __launch_bounds__(128, (MT == 64) ? 3 : 2)
tc_gemm(const __half* __restrict__ A, const __half* __restrict__ B,
        const float* __restrict__ bias,
        float* __restrict__ Cf, int ldc,
        __half* __restrict__ Ch, int ldh, int K,
        const float* __restrict__ aux, const float* __restrict__ xlin) {
    extern __shared__ char dsm[];
    const uint32_t base = (smem_u32(dsm) + 1023u) & ~1023u;
    constexpr int FM = MT / 32;          // m16 fragments per warp

    const int tid  = threadIdx.x;
    const int wid  = tid >> 5, lane = tid & 31;
    const int wm   = wid & 1;            // 2 m-warps * (MT/2) rows
    const int wn   = wid >> 1;           // 2 n-warps * 64 cols
    const int m0   = blockIdx.y * MT, n0 = blockIdx.x * 128;
    const int row_r = tid >> 3, c16 = (tid & 7) * 16;
    const uint32_t stage_bytes = (uint32_t)(MT * 128 + 16384);

    const int NKB = K >> 6;
    const char* Ab = (const char*)A + (size_t)m0 * K * 2;
    const char* Bb = (const char*)B + (size_t)n0 * K * 2;
    const size_t rstride = (size_t)K * 2;

    const int ar = lane & 15;
    const int ac = (lane >> 4) * 16;
    const int br = lane & 7;
    const int bn = ((lane >> 4) & 1) * 8;
    const int bc = ((lane >> 3) & 1) * 16;

    float acc[FM][8][4];
#pragma unroll
    for (int i = 0; i < FM; i++)
#pragma unroll
        for (int j = 0; j < 8; j++)
#pragma unroll
            for (int e = 0; e < 4; e++) acc[i][j][e] = 0.f;

    for (int s = 0; s < STAGES - 1 && s < NKB; s++) {
        load_stage<MT>(base, s, s, Ab, Bb, rstride, row_r, c16);
        cp_commit();
    }

    for (int kb = 0; kb < NKB; kb++) {
        const int st = kb % STAGES;
        cp_wait<STAGES - 2>();
        __syncthreads();

        const uint32_t sA = base + (uint32_t)st * stage_bytes;
        const uint32_t sB = sA + (uint32_t)(MT * 128);
#pragma unroll
        for (int ks = 0; ks < 4; ks++) {
            const int kbyte = ks * 32;
            uint32_t a[FM][4];
#pragma unroll
            for (int fm = 0; fm < FM; fm++) {
                uint32_t ad = sA + SWZ((uint32_t)((wm * (MT / 2) + fm * 16 + ar) * 128 + kbyte + ac));
                ldm_x4(a[fm][0], a[fm][1], a[fm][2], a[fm][3], ad);
            }
#pragma unroll
            for (int g = 0; g < 4; g++) {
                uint32_t b0, b1, b2, b3;
                uint32_t bd = sB + SWZ((uint32_t)((wn * 64 + g * 16 + bn + br) * 128 + kbyte + bc));
                ldm_x4(b0, b1, b2, b3, bd);
#pragma unroll
                for (int fm = 0; fm < FM; fm++) {
                    mma16816(acc[fm][2 * g],     a[fm], b0, b1);
                    mma16816(acc[fm][2 * g + 1], a[fm], b2, b3);
                }
            }
        }
        // slot refilled below was consumed last iteration; fenced by the
        // post-wait __syncthreads() above.
        const int nk = kb + STAGES - 1;
        if (nk < NKB)
            load_stage<MT>(base, nk % STAGES, nk, Ab, Bb, rstride, row_r, c16);
        cp_commit();
    }

    // ---------------- epilogue (register accumulators) ----------------
    const int er = lane >> 2;
    const int ec = (lane & 3) * 2;
    float fs[FM][2];
    if (EPI == 6) {
#pragma unroll
        for (int i = 0; i < FM; i++) { fs[i][0] = 0.f; fs[i][1] = 0.f; }
    }
#pragma unroll
    for (int fm = 0; fm < FM; fm++) {
#pragma unroll
        for (int fn = 0; fn < 8; fn++) {
            const int ng = n0 + wn * 64 + fn * 8 + ec;
#pragma unroll
            for (int rr = 0; rr < 2; rr++) {
                const int m = m0 + wm * (MT / 2) + fm * 16 + er + rr * 8;
                float v0 = acc[fm][fn][rr * 2 + 0];
                float v1 = acc[fm][fn][rr * 2 + 1];
                if (EPI == 4 || EPI == 6 || EPI == 7) {
                    v0 += bias[ng];     v0 = v0 > 0.f ? v0 : 0.f;
                    v1 += bias[ng + 1]; v1 = v1 > 0.f ? v1 : 0.f;
                }
                if (EPI == 2) {
                    size_t o = (size_t)m * ldc + ng;
                    float2 cb = *(const float2*)(aux + o);
                    float2 xb = *(const float2*)(xlin + o);
                    v0 = cb.x * (v0 + bias[ng])     + xb.x;
                    v1 = cb.y * (v1 + bias[ng + 1]) + xb.y;
                    *(float2*)(Cf + o) = make_float2(v0, v1);
                }
                if (EPI == 7)
                    *(float2*)(Cf + (size_t)m * ldc + ng) = make_float2(v0, v1);
                if (EPI == 6)
                    fs[fm][rr] += v0 * aux[ng] + v1 * aux[ng + 1];
                if (EPI == 2 || EPI == 3 || EPI == 4 || EPI == 7)
                    half_store2(Ch, (size_t)m * ldh + ng, v0, v1);
            }
        }
    }
    if (EPI == 6) {
#pragma unroll
        for (int fm = 0; fm < FM; fm++)
#pragma unroll
            for (int rr = 0; rr < 2; rr++) {
                float s = fs[fm][rr];
                s += __shfl_xor_sync(0xffffffffu, s, 1);
                s += __shfl_xor_sync(0xffffffffu, s, 2);
                if ((lane & 3) == 0) {
                    const int m = m0 + wm * (MT / 2) + fm * 16 + er + rr * 8;
                    atomicAdd(&Cf[m], s);
                }
            }
    }
}

// ==================== fp32 SGEMM (bottom layer 1 only, K=13) ===============
// relu -> fp16 Ch only.
__global__ void __launch_bounds__(256, 2)
sgemm_l1(const float* __restrict__ A, int lda,
         const float* __restrict__ Bm, int ldb,
         const float* __restrict__ bias,
         int ldc, int K,
         __half* __restrict__ Ch) {
    __shared__ __align__(16) float As[8][128];
    __shared__ __align__(16) float Bs[8][128];
    const int tid = threadIdx.x;
    const int m0 = blockIdx.y * 128, n0 = blockIdx.x * 128;
    const int lr = tid >> 1, lc = (tid & 1) * 4;
    const float* Ag = A + (size_t)(m0 + lr) * lda + lc;
    const float* Bg = Bm + (size_t)(n0 + lr) * ldb + lc;
    const int ty = tid >> 4, tx = tid & 15;

    float acc[8][8];
#pragma unroll
    for (int i = 0; i < 8; i++)
#pragma unroll
        for (int j = 0; j < 8; j++) acc[i][j] = 0.f;

    for (int k0 = 0; k0 < K; k0 += 8) {
#pragma unroll
        for (int j = 0; j < 4; j++) {
            int kk = k0 + lc + j;
            As[lc + j][lr] = (kk < K) ? Ag[k0 + j] : 0.f;
            Bs[lc + j][lr] = (kk < K) ? Bg[k0 + j] : 0.f;
        }
        __syncthreads();
#pragma unroll
        for (int k = 0; k < 8; k++) {
            float4 a0 = *(const float4*)&As[k][ty * 4];
            float4 a1 = *(const float4*)&As[k][64 + ty * 4];
            float4 b0 = *(const float4*)&Bs[k][tx * 4];
            float4 b1 = *(const float4*)&Bs[k][64 + tx * 4];
            float af[8] = {a0.x, a0.y, a0.z, a0.w, a1.x, a1.y, a1.z, a1.w};
            float bf[8] = {b0.x, b0.y, b0.z, b0.w, b1.x, b1.y, b1.z, b1.w};
#pragma unroll
            for (int i = 0; i < 8; i++)
#pragma unroll
                for (int j = 0; j < 8; j++) acc[i][j] += af[i] * bf[j];
        }
        __syncthreads();
    }
#pragma unroll
    for (int i = 0; i < 8; i++) {
        int mg = m0 + ((i < 4) ? (ty * 4 + i) : (64 + ty * 4 + (i - 4)));
        size_t rowoff = (size_t)mg * ldc;
#pragma unroll
        for (int j = 0; j < 8; j++) {
            int ng = n0 + ((j < 4) ? (tx * 4 + j) : (64 + tx * 4 + (j - 4)));
            float v = acc[i][j] + bias[ng];
            v = v > 0.f ? v : 0.f;
            Ch[rowoff + ng] = __float2half_rn(v);
        }
    }
}

// ==================== launch ====================
extern "C" void kernel_launch(void* const* d_in, const int* in_sizes, int n_in,
                              void* d_out, int out_size) {
    const float* dense   = (const float*)d_in[0];
    const void*  indices = d_in[1];
    const void*  offsets = d_in[2];
    const float* emb     = (const float*)d_in[3];
    const float* bW0 = (const float*)d_in[4];  const float* bb0 = (const float*)d_in[5];
    const float* bW1 = (const float*)d_in[6];  const float* bb1 = (const float*)d_in[7];
    const float* bW2 = (const float*)d_in[8];  const float* bb2 = (const float*)d_in[9];
    const float* dcnW = (const float*)d_in[10];
    const float* dcnV = (const float*)d_in[11];
    const float* dcnb = (const float*)d_in[12];
    const float* tW0 = (const float*)d_in[13]; const float* tb0 = (const float*)d_in[14];
    const float* tW1 = (const float*)d_in[15]; const float* tb1 = (const float*)d_in[16];
    const float* tW2 = (const float*)d_in[17]; const float* tb2 = (const float*)d_in[18];
    const float* tW3 = (const float*)d_in[19]; const float* tb3 = (const float*)d_in[20];

    float *comb, *xl;
    __half *actA, *z0h, *z1h, *xvh, *wV, *wW, *wT0, *wT1, *wT2, *wB1, *wB2;
    cudaGetSymbolAddress((void**)&comb, g_comb);
    cudaGetSymbolAddress((void**)&xl,   g_xl);
    cudaGetSymbolAddress((void**)&actA, g_actA);
    cudaGetSymbolAddress((void**)&z0h,  g_z0h);
    cudaGetSymbolAddress((void**)&z1h,  g_z1h);
    cudaGetSymbolAddress((void**)&xvh,  g_xvh);
    cudaGetSymbolAddress((void**)&wV,   g_wV);
    cudaGetSymbolAddress((void**)&wW,   g_wW);
    cudaGetSymbolAddress((void**)&wT0,  g_wT0);
    cudaGetSymbolAddress((void**)&wT1,  g_wT1);
    cudaGetSymbolAddress((void**)&wT2,  g_wT2);
    cudaGetSymbolAddress((void**)&wB1,  g_wB1);
    cudaGetSymbolAddress((void**)&wB2,  g_wB2);

    const int dynsmem128 = STAGES * 32768 + 1024;
    const int dynsmem64  = STAGES * 24576 + 1024;
    cudaFuncSetAttribute(tc_gemm<2,128>, cudaFuncAttributeMaxDynamicSharedMemorySize, dynsmem128);
    cudaFuncSetAttribute(tc_gemm<3,64>,  cudaFuncAttributeMaxDynamicSharedMemorySize, dynsmem64);
    cudaFuncSetAttribute(tc_gemm<4,128>, cudaFuncAttributeMaxDynamicSharedMemorySize, dynsmem128);
    cudaFuncSetAttribute(tc_gemm<6,64>,  cudaFuncAttributeMaxDynamicSharedMemorySize, dynsmem64);
    cudaFuncSetAttribute(tc_gemm<7,128>, cudaFuncAttributeMaxDynamicSharedMemorySize, dynsmem128);

    // --- side stream for the compute chain (conversion + bottom MLP),
    //     overlapped with the DRAM-bound pooling on the main stream.
    cudaStream_t s1;
    cudaEvent_t evFork, evJoin;
    cudaStreamCreateWithFlags(&s1, cudaStreamNonBlocking);
    cudaEventCreateWithFlags(&evFork, cudaEventDisableTiming);
    cudaEventCreateWithFlags(&evJoin, cudaEventDisableTiming);

    cudaEventRecord(evFork, 0);
    cudaStreamWaitEvent(s1, evFork, 0);

    // s1: weight conversion + out-init, then bottom MLP into comb/actA cols 0-127
    ConvArgs ca;
    ca.src[0] = dcnV; ca.dst[0] = wV;  ca.n[0] = 3 * LOWR * FIN;
    ca.src[1] = dcnW; ca.dst[1] = wW;  ca.n[1] = 3 * FIN * LOWR;
    ca.src[2] = tW0;  ca.dst[2] = wT0; ca.n[2] = 1024 * FIN;
    ca.src[3] = tW1;  ca.dst[3] = wT1; ca.n[3] = 1024 * 1024;
    ca.src[4] = tW2;  ca.dst[4] = wT2; ca.n[4] = 512 * 1024;
    ca.src[5] = bW1;  ca.dst[5] = wB1; ca.n[5] = 256 * 512;
    ca.src[6] = bW2;  ca.dst[6] = wB2; ca.n[6] = 128 * 256;
    ca.total = ca.n[0] + ca.n[1] + ca.n[2] + ca.n[3] + ca.n[4] + ca.n[5] + ca.n[6];
    ca.out = (float*)d_out;
    ca.b3 = tb3;
    conv_kernel<<<2048, 256, 0, s1>>>(ca);
    sgemm_l1<<<dim3(4, 32), 256, 0, s1>>>(dense, 13, bW0, 13, bb0, 512, 13, z0h);
    tc_gemm<4,128><<<dim3(2, 32), 128, dynsmem128, s1>>>(
        z0h, wB1, bb1, nullptr, 0, z1h, 256, 512, nullptr, nullptr);
    tc_gemm<7,128><<<dim3(1, 32), 128, dynsmem128, s1>>>(
        z1h, wB2, bb2, comb, FIN, actA, FIN, 256, nullptr, nullptr);
    cudaEventRecord(evJoin, s1);

    // main stream: dtype detect + pooling into comb/actA cols 128..3455
    detect_kernel<<<1, 256>>>((const unsigned*)offsets, in_sizes[2]);
    pool_kernel<<<(NTAB * BATCH) / 8, 256>>>(indices, offsets, emb, comb, actA);

    // join: DCN needs full actA/comb and converted weights
    cudaStreamWaitEvent(0, evJoin, 0);

    // --- low-rank DCN (fp16 GEMMs; x_l master in fp32, fp16 feed in actA)
    for (int l = 0; l < 3; l++) {
        const float* xlin = (l == 0) ? comb : xl;
        tc_gemm<3,64><<<dim3(LOWR / 128, 64), 128, dynsmem64>>>(
            actA, wV + (size_t)l * LOWR * FIN, nullptr, nullptr, 0,
            xvh, LOWR, FIN, nullptr, nullptr);
        tc_gemm<2,128><<<dim3(FIN / 128, 32), 128, dynsmem128>>>(
            xvh, wW + (size_t)l * FIN * LOWR, dcnb + (size_t)l * FIN, xl, FIN,
            actA, FIN, LOWR, comb, xlin);
    }

    // --- top MLP: 3456 -> 1024 -> 1024 -> 512 (relu) -> 1 (fused dot)
    tc_gemm<4,128><<<dim3(8, 32), 128, dynsmem128>>>(
        actA, wT0, tb0, nullptr, 0, z0h, 1024, FIN, nullptr, nullptr);
    tc_gemm<4,128><<<dim3(8, 32), 128, dynsmem128>>>(
        z0h, wT1, tb1, nullptr, 0, z1h, 1024, 1024, nullptr, nullptr);
    tc_gemm<6,64><<<dim3(4, 64), 128, dynsmem64>>>(
        z1h, wT2, tb2, (float*)d_out, 0, nullptr, 0, 1024, tW3, nullptr);
}